// round 2
// baseline (speedup 1.0000x reference)
#include <cuda_runtime.h>
#include <cstddef>

#define D 64
#define NMAX 100000

// Scratch (no allocation allowed -> device globals)
__device__ float g_h[(size_t)NMAX * D];
__device__ float g_agg[(size_t)NMAX * D];
__device__ float g_t2[(size_t)NMAX * D];
__device__ float g_stats[5 * 2 * D];  // per BN: [sum(64), sumsq(64)]

// ---------------------------------------------------------------------------
// zero the stats buffer (must happen every replay)
__global__ void zero_stats_kernel() {
    int i = threadIdx.x;
    if (i < 5 * 2 * D) g_stats[i] = 0.f;
}

// ---------------------------------------------------------------------------
// layer-0 prep: h = x ; agg = x
__global__ void prep0_kernel(const float* __restrict__ x, int total4) {
    int i = blockIdx.x * blockDim.x + threadIdx.x;
    if (i >= total4) return;
    float4 v = ((const float4*)x)[i];
    ((float4*)g_h)[i] = v;
    ((float4*)g_agg)[i] = v;
}

// ---------------------------------------------------------------------------
// scatter: agg[dst] += h[src] over all edges.
// 16 threads per edge, float4 per thread, vector red.global (sm_90+).
// edge_index is int32 (JAX downcasts int64 without x64 mode).
__global__ void scatter_kernel(const int* __restrict__ ei, int E) {
    long long t = (long long)blockIdx.x * blockDim.x + threadIdx.x;
    int e = (int)(t >> 4);
    if (e >= E) return;
    int c = (int)(t & 15) << 2;
    int s = __ldg(ei + e);
    int d = __ldg(ei + E + e);
    float4 v = *(const float4*)(g_h + (size_t)s * D + c);
    float* p = g_agg + (size_t)d * D + c;
    asm volatile("red.global.add.v4.f32 [%0], {%1,%2,%3,%4};"
                 :: "l"(p), "f"(v.x), "f"(v.y), "f"(v.z), "f"(v.w)
                 : "memory");
}

// ---------------------------------------------------------------------------
// Fused MLP: out = relu( relu(A@W1 + b1) @ W2 + b2 )   (TWO=true)
//        or  out = relu( A@W1 + b1 )                   (TWO=false, head GEMM)
// plus per-column sum / sumsq accumulation into stats (for BatchNorm).
// Tile: 64 rows per block, 256 threads, 4x4 register tile each.
template <bool TWO>
__global__ void __launch_bounds__(256) mlp_kernel(
    const float* __restrict__ A,
    const float* __restrict__ W1, const float* __restrict__ b1,
    const float* __restrict__ W2, const float* __restrict__ b2,
    float* __restrict__ out, float* __restrict__ stats, int nrows)
{
    __shared__ float sW[64 * 64];     // weight tile
    __shared__ float sA[64 * 65];     // A (then t1) tile, padded row stride

    const int t = threadIdx.x;
    const int row0 = blockIdx.x * 64;

    // load W1
    for (int i = t; i < 1024; i += 256)
        ((float4*)sW)[i] = ((const float4*)W1)[i];

    // load A tile (row-major, stride 65)
    for (int i = t; i < 1024; i += 256) {
        int r  = i >> 4;
        int k4 = (i & 15) << 2;
        float4 v = make_float4(0.f, 0.f, 0.f, 0.f);
        if (row0 + r < nrows)
            v = *(const float4*)(A + (size_t)(row0 + r) * D + k4);
        sA[r * 65 + k4 + 0] = v.x;
        sA[r * 65 + k4 + 1] = v.y;
        sA[r * 65 + k4 + 2] = v.z;
        sA[r * 65 + k4 + 3] = v.w;
    }
    __syncthreads();

    const int cg = (t & 15) << 2;   // column base (0..60)
    const int rg = (t >> 4) << 2;   // row base    (0..60)

    float acc[4][4];
#pragma unroll
    for (int r = 0; r < 4; r++)
#pragma unroll
        for (int c = 0; c < 4; c++) acc[r][c] = 0.f;

#pragma unroll 16
    for (int k = 0; k < 64; k++) {
        float4 w = *(const float4*)(sW + k * 64 + cg);
        float a0 = sA[(rg + 0) * 65 + k];
        float a1 = sA[(rg + 1) * 65 + k];
        float a2 = sA[(rg + 2) * 65 + k];
        float a3 = sA[(rg + 3) * 65 + k];
        acc[0][0] += a0 * w.x; acc[0][1] += a0 * w.y; acc[0][2] += a0 * w.z; acc[0][3] += a0 * w.w;
        acc[1][0] += a1 * w.x; acc[1][1] += a1 * w.y; acc[1][2] += a1 * w.z; acc[1][3] += a1 * w.w;
        acc[2][0] += a2 * w.x; acc[2][1] += a2 * w.y; acc[2][2] += a2 * w.z; acc[2][3] += a2 * w.w;
        acc[3][0] += a3 * w.x; acc[3][1] += a3 * w.y; acc[3][2] += a3 * w.z; acc[3][3] += a3 * w.w;
    }

    if (TWO) {
        __syncthreads();   // all reads of sW/sA done
        // t1 = relu(acc + b1) back into sA
        float bb[4];
#pragma unroll
        for (int c = 0; c < 4; c++) bb[c] = b1[cg + c];
#pragma unroll
        for (int r = 0; r < 4; r++)
#pragma unroll
            for (int c = 0; c < 4; c++)
                sA[(rg + r) * 65 + cg + c] = fmaxf(acc[r][c] + bb[c], 0.f);
        // load W2
        for (int i = t; i < 1024; i += 256)
            ((float4*)sW)[i] = ((const float4*)W2)[i];
        __syncthreads();

#pragma unroll
        for (int r = 0; r < 4; r++)
#pragma unroll
            for (int c = 0; c < 4; c++) acc[r][c] = 0.f;

#pragma unroll 16
        for (int k = 0; k < 64; k++) {
            float4 w = *(const float4*)(sW + k * 64 + cg);
            float a0 = sA[(rg + 0) * 65 + k];
            float a1 = sA[(rg + 1) * 65 + k];
            float a2 = sA[(rg + 2) * 65 + k];
            float a3 = sA[(rg + 3) * 65 + k];
            acc[0][0] += a0 * w.x; acc[0][1] += a0 * w.y; acc[0][2] += a0 * w.z; acc[0][3] += a0 * w.w;
            acc[1][0] += a1 * w.x; acc[1][1] += a1 * w.y; acc[1][2] += a1 * w.z; acc[1][3] += a1 * w.w;
            acc[2][0] += a2 * w.x; acc[2][1] += a2 * w.y; acc[2][2] += a2 * w.z; acc[2][3] += a2 * w.w;
            acc[3][0] += a3 * w.x; acc[3][1] += a3 * w.y; acc[3][2] += a3 * w.z; acc[3][3] += a3 * w.w;
        }
    }

    // epilogue: bias + relu + store + BN stats
    const float* bias = TWO ? b2 : b1;
    float bx = bias[cg + 0], by = bias[cg + 1], bz = bias[cg + 2], bw = bias[cg + 3];
    float cs[4] = {0.f, 0.f, 0.f, 0.f};
    float cq[4] = {0.f, 0.f, 0.f, 0.f};
#pragma unroll
    for (int r = 0; r < 4; r++) {
        int gr = row0 + rg + r;
        if (gr < nrows) {
            float4 o;
            o.x = fmaxf(acc[r][0] + bx, 0.f);
            o.y = fmaxf(acc[r][1] + by, 0.f);
            o.z = fmaxf(acc[r][2] + bz, 0.f);
            o.w = fmaxf(acc[r][3] + bw, 0.f);
            *(float4*)(out + (size_t)gr * D + cg) = o;
            cs[0] += o.x; cq[0] += o.x * o.x;
            cs[1] += o.y; cq[1] += o.y * o.y;
            cs[2] += o.z; cq[2] += o.z * o.z;
            cs[3] += o.w; cq[3] += o.w * o.w;
        }
    }
    // lane L and L+16 share the same column group -> one shfl reduce
#pragma unroll
    for (int c = 0; c < 4; c++) {
        cs[c] += __shfl_down_sync(0xffffffffu, cs[c], 16);
        cq[c] += __shfl_down_sync(0xffffffffu, cq[c], 16);
    }
    if ((t & 31) < 16) {
#pragma unroll
        for (int c = 0; c < 4; c++) {
            atomicAdd(stats + cg + c, cs[c]);
            atomicAdd(stats + D + cg + c, cq[c]);
        }
    }
}

// ---------------------------------------------------------------------------
// BatchNorm apply: y = g*(x-m)*rsqrt(var+eps)+b ; writes o1 (and o2 if given)
__global__ void bn_apply_kernel(const float* __restrict__ in,
                                const float* __restrict__ stats,
                                const float* __restrict__ g,
                                const float* __restrict__ b,
                                float* __restrict__ o1, float* __restrict__ o2,
                                float invN, int total4)
{
    int i = blockIdx.x * blockDim.x + threadIdx.x;
    if (i >= total4) return;
    int c = (i << 2) & 63;
    float4 v = ((const float4*)in)[i];
    float4 y;
#pragma unroll
    for (int j = 0; j < 4; j++) {
        float m  = stats[c + j] * invN;
        float e2 = stats[D + c + j] * invN;
        float var = e2 - m * m;
        float sc = g[c + j] * rsqrtf(var + 1e-5f);
        float sh = b[c + j] - m * sc;
        float xv = (&v.x)[j];
        (&y.x)[j] = xv * sc + sh;
    }
    ((float4*)o1)[i] = y;
    if (o2) ((float4*)o2)[i] = y;
}

// ---------------------------------------------------------------------------
extern "C" void kernel_launch(void* const* d_in, const int* in_sizes, int n_in,
                              void* d_out, int out_size)
{
    const float* x      = (const float*)d_in[0];
    const int*   ei     = (const int*)d_in[1];   // int32 (JAX downcast)
    const float* W1     = (const float*)d_in[3];
    const float* b1     = (const float*)d_in[4];
    const float* W2     = (const float*)d_in[5];
    const float* b2     = (const float*)d_in[6];
    const float* bng    = (const float*)d_in[7];
    const float* bnb    = (const float*)d_in[8];
    const float* muW    = (const float*)d_in[9];
    const float* mub    = (const float*)d_in[10];
    const float* lvW    = (const float*)d_in[11];
    const float* lvb    = (const float*)d_in[12];
    const float* mug    = (const float*)d_in[13];
    const float* mubeta = (const float*)d_in[14];
    const float* lvg    = (const float*)d_in[15];
    const float* lvbeta = (const float*)d_in[16];
    float* out = (float*)d_out;

    const int n = in_sizes[0] / D;
    const int E = in_sizes[1] / 2;
    const float invN = 1.0f / (float)n;
    const int total4 = n * (D / 4);
    const int vb = (total4 + 255) / 256;
    const int gb = (n + 63) / 64;
    const int eb = (int)(((long long)E * 16 + 255) / 256);

    float *hbuf, *abuf, *tbuf, *sbuf;
    cudaGetSymbolAddress((void**)&hbuf, g_h);
    cudaGetSymbolAddress((void**)&abuf, g_agg);
    cudaGetSymbolAddress((void**)&tbuf, g_t2);
    cudaGetSymbolAddress((void**)&sbuf, g_stats);

    zero_stats_kernel<<<1, 640>>>();
    prep0_kernel<<<vb, 256>>>(x, total4);

    for (int l = 0; l < 3; l++) {
        scatter_kernel<<<eb, 256>>>(ei, E);
        mlp_kernel<true><<<gb, 256>>>(abuf,
                                      W1 + l * 4096, b1 + l * 64,
                                      W2 + l * 4096, b2 + l * 64,
                                      tbuf, sbuf + l * 128, n);
        bn_apply_kernel<<<vb, 256>>>(tbuf, sbuf + l * 128,
                                     bng + l * 64, bnb + l * 64,
                                     hbuf, abuf, invN, total4);
    }

    // mu head
    mlp_kernel<false><<<gb, 256>>>(hbuf, muW, mub, nullptr, nullptr,
                                   abuf, sbuf + 3 * 128, n);
    bn_apply_kernel<<<vb, 256>>>(abuf, sbuf + 3 * 128, mug, mubeta,
                                 out, nullptr, invN, total4);
    // logvar head
    mlp_kernel<false><<<gb, 256>>>(hbuf, lvW, lvb, nullptr, nullptr,
                                   tbuf, sbuf + 4 * 128, n);
    bn_apply_kernel<<<vb, 256>>>(tbuf, sbuf + 4 * 128, lvg, lvbeta,
                                 out + (size_t)n * D, nullptr, invN, total4);
}

// round 4
// speedup vs baseline: 1.5859x; 1.5859x over previous
#include <cuda_runtime.h>
#include <cstddef>

#define D 64
#define NMAX 100000

// Scratch (no allocation allowed -> device globals)
__device__ float g_h[(size_t)NMAX * D];
__device__ float g_agg[(size_t)NMAX * D];
__device__ float g_t2[(size_t)NMAX * D];
__device__ float g_stats[5 * 2 * D];  // per BN: [sum(64), sumsq(64)]

// ---------------------------------------------------------------------------
__global__ void zero_stats_kernel() {
    int i = threadIdx.x;
    if (i < 5 * 2 * D) g_stats[i] = 0.f;
}

// ---------------------------------------------------------------------------
// layer-0 prep: h = x ; agg = x
__global__ void prep0_kernel(const float* __restrict__ x, int total4) {
    int i = blockIdx.x * blockDim.x + threadIdx.x;
    if (i >= total4) return;
    float4 v = ((const float4*)x)[i];
    ((float4*)g_h)[i] = v;
    ((float4*)g_agg)[i] = v;
}

// ---------------------------------------------------------------------------
// scatter: agg[dst] += h[src]; 16 threads/edge, float4 + red.global.v4
__global__ void scatter_kernel(const int* __restrict__ ei, int E) {
    long long t = (long long)blockIdx.x * blockDim.x + threadIdx.x;
    int e = (int)(t >> 4);
    if (e >= E) return;
    int c = (int)(t & 15) << 2;
    int s = __ldg(ei + e);
    int d = __ldg(ei + E + e);
    float4 v = *(const float4*)(g_h + (size_t)s * D + c);
    float* p = g_agg + (size_t)d * D + c;
    asm volatile("red.global.add.v4.f32 [%0], {%1,%2,%3,%4};"
                 :: "l"(p), "f"(v.x), "f"(v.y), "f"(v.z), "f"(v.w)
                 : "memory");
}

// ---------------------------------------------------------------------------
// Fused MLP: out = relu( relu(A@W1+b1) @ W2 + b2 )  (TWO) or relu(A@W1+b1)
// + per-column sum/sumsq for BatchNorm.
// 128-row tile, 256 threads, 8x4 register tile, k-contiguous A tile so the
// k-loop uses float4 LDS along k. sA reads are warp broadcasts (2 addrs/warp)
// so no padding needed -> exactly 48KB static smem.
#define SAPITCH 64
template <bool TWO>
__global__ void __launch_bounds__(256, 2) mlp_kernel(
    const float* __restrict__ A,
    const float* __restrict__ W1, const float* __restrict__ b1,
    const float* __restrict__ W2, const float* __restrict__ b2,
    float* __restrict__ out, float* __restrict__ stats, int nrows)
{
    __shared__ float sW[64 * 64];          // weight tile [k][n]  (16 KB)
    __shared__ float sA[128 * SAPITCH];    // A / t1 tile [row][k] (32 KB)

    const int t = threadIdx.x;
    const int row0 = blockIdx.x * 128;

    for (int i = t; i < 1024; i += 256)
        ((float4*)sW)[i] = ((const float4*)W1)[i];

    for (int i = t; i < 2048; i += 256) {
        int r  = i >> 4;
        int k4 = (i & 15) << 2;
        float4 v = make_float4(0.f, 0.f, 0.f, 0.f);
        if (row0 + r < nrows)
            v = *(const float4*)(A + (size_t)(row0 + r) * D + k4);
        *(float4*)(sA + r * SAPITCH + k4) = v;
    }
    __syncthreads();

    const int cg = (t & 15) << 2;   // column base (0..60)
    const int rg = (t >> 4) << 3;   // row base    (0..120)

    float acc[8][4];
#pragma unroll
    for (int r = 0; r < 8; r++)
#pragma unroll
        for (int c = 0; c < 4; c++) acc[r][c] = 0.f;

#pragma unroll 2
    for (int k0 = 0; k0 < 64; k0 += 4) {
        float4 w[4];
#pragma unroll
        for (int j = 0; j < 4; j++)
            w[j] = *(const float4*)(sW + (k0 + j) * 64 + cg);
#pragma unroll
        for (int r = 0; r < 8; r++) {
            float4 a = *(const float4*)(sA + (rg + r) * SAPITCH + k0);
#pragma unroll
            for (int c = 0; c < 4; c++) {
                float v = acc[r][c];
                v = fmaf(a.x, (&w[0].x)[c], v);
                v = fmaf(a.y, (&w[1].x)[c], v);
                v = fmaf(a.z, (&w[2].x)[c], v);
                v = fmaf(a.w, (&w[3].x)[c], v);
                acc[r][c] = v;
            }
        }
    }

    if (TWO) {
        __syncthreads();   // all reads of sW/sA done
        float bb[4];
#pragma unroll
        for (int c = 0; c < 4; c++) bb[c] = b1[cg + c];
#pragma unroll
        for (int r = 0; r < 8; r++) {
            float4 o;
#pragma unroll
            for (int c = 0; c < 4; c++)
                (&o.x)[c] = fmaxf(acc[r][c] + bb[c], 0.f);
            *(float4*)(sA + (rg + r) * SAPITCH + cg) = o;
        }
        for (int i = t; i < 1024; i += 256)
            ((float4*)sW)[i] = ((const float4*)W2)[i];
        __syncthreads();

#pragma unroll
        for (int r = 0; r < 8; r++)
#pragma unroll
            for (int c = 0; c < 4; c++) acc[r][c] = 0.f;

#pragma unroll 2
        for (int k0 = 0; k0 < 64; k0 += 4) {
            float4 w[4];
#pragma unroll
            for (int j = 0; j < 4; j++)
                w[j] = *(const float4*)(sW + (k0 + j) * 64 + cg);
#pragma unroll
            for (int r = 0; r < 8; r++) {
                float4 a = *(const float4*)(sA + (rg + r) * SAPITCH + k0);
#pragma unroll
                for (int c = 0; c < 4; c++) {
                    float v = acc[r][c];
                    v = fmaf(a.x, (&w[0].x)[c], v);
                    v = fmaf(a.y, (&w[1].x)[c], v);
                    v = fmaf(a.z, (&w[2].x)[c], v);
                    v = fmaf(a.w, (&w[3].x)[c], v);
                    acc[r][c] = v;
                }
            }
        }
    }

    // epilogue: bias + relu + store + BN stats
    const float* bias = TWO ? b2 : b1;
    float bx = bias[cg + 0], by = bias[cg + 1], bz = bias[cg + 2], bw = bias[cg + 3];
    float cs[4] = {0.f, 0.f, 0.f, 0.f};
    float cq[4] = {0.f, 0.f, 0.f, 0.f};
#pragma unroll
    for (int r = 0; r < 8; r++) {
        int gr = row0 + rg + r;
        if (gr < nrows) {
            float4 o;
            o.x = fmaxf(acc[r][0] + bx, 0.f);
            o.y = fmaxf(acc[r][1] + by, 0.f);
            o.z = fmaxf(acc[r][2] + bz, 0.f);
            o.w = fmaxf(acc[r][3] + bw, 0.f);
            *(float4*)(out + (size_t)gr * D + cg) = o;
            cs[0] += o.x; cq[0] += o.x * o.x;
            cs[1] += o.y; cq[1] += o.y * o.y;
            cs[2] += o.z; cq[2] += o.z * o.z;
            cs[3] += o.w; cq[3] += o.w * o.w;
        }
    }
    // lanes L and L+16 share the same column group -> one shfl reduce
#pragma unroll
    for (int c = 0; c < 4; c++) {
        cs[c] += __shfl_down_sync(0xffffffffu, cs[c], 16);
        cq[c] += __shfl_down_sync(0xffffffffu, cq[c], 16);
    }
    if ((t & 31) < 16) {
#pragma unroll
        for (int c = 0; c < 4; c++) {
            atomicAdd(stats + cg + c, cs[c]);
            atomicAdd(stats + D + cg + c, cq[c]);
        }
    }
}

// ---------------------------------------------------------------------------
// BatchNorm apply: y = g*(x-m)*rsqrt(var+eps)+b ; writes o1 (and o2 if given)
__global__ void bn_apply_kernel(const float* __restrict__ in,
                                const float* __restrict__ stats,
                                const float* __restrict__ g,
                                const float* __restrict__ b,
                                float* __restrict__ o1, float* __restrict__ o2,
                                float invN, int total4)
{
    int i = blockIdx.x * blockDim.x + threadIdx.x;
    if (i >= total4) return;
    int c = (i << 2) & 63;
    float4 v = ((const float4*)in)[i];
    float4 y;
#pragma unroll
    for (int j = 0; j < 4; j++) {
        float m  = stats[c + j] * invN;
        float e2 = stats[D + c + j] * invN;
        float var = e2 - m * m;
        float sc = g[c + j] * rsqrtf(var + 1e-5f);
        float sh = b[c + j] - m * sc;
        float xv = (&v.x)[j];
        (&y.x)[j] = xv * sc + sh;
    }
    ((float4*)o1)[i] = y;
    if (o2) ((float4*)o2)[i] = y;
}

// ---------------------------------------------------------------------------
extern "C" void kernel_launch(void* const* d_in, const int* in_sizes, int n_in,
                              void* d_out, int out_size)
{
    const float* x      = (const float*)d_in[0];
    const int*   ei     = (const int*)d_in[1];   // int32 (JAX downcast)
    const float* W1     = (const float*)d_in[3];
    const float* b1     = (const float*)d_in[4];
    const float* W2     = (const float*)d_in[5];
    const float* b2     = (const float*)d_in[6];
    const float* bng    = (const float*)d_in[7];
    const float* bnb    = (const float*)d_in[8];
    const float* muW    = (const float*)d_in[9];
    const float* mub    = (const float*)d_in[10];
    const float* lvW    = (const float*)d_in[11];
    const float* lvb    = (const float*)d_in[12];
    const float* mug    = (const float*)d_in[13];
    const float* mubeta = (const float*)d_in[14];
    const float* lvg    = (const float*)d_in[15];
    const float* lvbeta = (const float*)d_in[16];
    float* out = (float*)d_out;

    const int n = in_sizes[0] / D;
    const int E = in_sizes[1] / 2;
    const float invN = 1.0f / (float)n;
    const int total4 = n * (D / 4);
    const int vb = (total4 + 255) / 256;
    const int gb = (n + 127) / 128;
    const int eb = (int)(((long long)E * 16 + 255) / 256);

    float *hbuf, *abuf, *tbuf, *sbuf;
    cudaGetSymbolAddress((void**)&hbuf, g_h);
    cudaGetSymbolAddress((void**)&abuf, g_agg);
    cudaGetSymbolAddress((void**)&tbuf, g_t2);
    cudaGetSymbolAddress((void**)&sbuf, g_stats);

    zero_stats_kernel<<<1, 640>>>();
    prep0_kernel<<<vb, 256>>>(x, total4);

    for (int l = 0; l < 3; l++) {
        scatter_kernel<<<eb, 256>>>(ei, E);
        mlp_kernel<true><<<gb, 256>>>(abuf,
                                      W1 + l * 4096, b1 + l * 64,
                                      W2 + l * 4096, b2 + l * 64,
                                      tbuf, sbuf + l * 128, n);
        bn_apply_kernel<<<vb, 256>>>(tbuf, sbuf + l * 128,
                                     bng + l * 64, bnb + l * 64,
                                     hbuf, abuf, invN, total4);
    }

    // mu head
    mlp_kernel<false><<<gb, 256>>>(hbuf, muW, mub, nullptr, nullptr,
                                   abuf, sbuf + 3 * 128, n);
    bn_apply_kernel<<<vb, 256>>>(abuf, sbuf + 3 * 128, mug, mubeta,
                                 out, nullptr, invN, total4);
    // logvar head
    mlp_kernel<false><<<gb, 256>>>(hbuf, lvW, lvb, nullptr, nullptr,
                                   tbuf, sbuf + 4 * 128, n);
    bn_apply_kernel<<<vb, 256>>>(tbuf, sbuf + 4 * 128, lvg, lvbeta,
                                 out + (size_t)n * D, nullptr, invN, total4);
}

// round 5
// speedup vs baseline: 3.2351x; 2.0398x over previous
#include <cuda_runtime.h>
#include <cstddef>
#include <cstdint>

#define D 64
#define NMAX 100000
#define SAP 68   // sA pitch: bank = (4*gid + tg) -> conflict-free frag loads

// Scratch (no allocation allowed -> device globals)
__device__ float g_h[(size_t)NMAX * D];
__device__ float g_agg[(size_t)NMAX * D];
__device__ float g_t2[(size_t)NMAX * D];
__device__ float g_stats[5 * 2 * D];  // per BN: [sum(64), sumsq(64)]

// ---------------------------------------------------------------------------
__global__ void zero_stats_kernel() {
    int i = threadIdx.x;
    if (i < 5 * 2 * D) g_stats[i] = 0.f;
}

// ---------------------------------------------------------------------------
__global__ void prep0_kernel(const float* __restrict__ x, int total4) {
    int i = blockIdx.x * blockDim.x + threadIdx.x;
    if (i >= total4) return;
    float4 v = ((const float4*)x)[i];
    ((float4*)g_h)[i] = v;
    ((float4*)g_agg)[i] = v;
}

// ---------------------------------------------------------------------------
// scatter: agg[dst] += h[src]; 16 threads/edge, float4 + red.global.v4
__global__ void scatter_kernel(const int* __restrict__ ei, int E) {
    long long t = (long long)blockIdx.x * blockDim.x + threadIdx.x;
    int e = (int)(t >> 4);
    if (e >= E) return;
    int c = (int)(t & 15) << 2;
    int s = __ldg(ei + e);
    int d = __ldg(ei + E + e);
    float4 v = *(const float4*)(g_h + (size_t)s * D + c);
    float* p = g_agg + (size_t)d * D + c;
    asm volatile("red.global.add.v4.f32 [%0], {%1,%2,%3,%4};"
                 :: "l"(p), "f"(v.x), "f"(v.y), "f"(v.z), "f"(v.w)
                 : "memory");
}

// ---------------------------------------------------------------------------
// tf32 helpers
__device__ __forceinline__ uint32_t f2tf(float x) {
    uint32_t r;
    asm("cvt.rna.tf32.f32 %0, %1;" : "=r"(r) : "f"(x));
    return r;
}
__device__ __forceinline__ void split_tf(float x, uint32_t& hi, uint32_t& lo) {
    hi = f2tf(x);
    lo = f2tf(x - __uint_as_float(hi));
}
__device__ __forceinline__ void mma_tf32(float* c, const uint32_t* a, const uint32_t* b) {
    asm volatile(
        "mma.sync.aligned.m16n8k8.row.col.f32.tf32.tf32.f32 "
        "{%0,%1,%2,%3}, {%4,%5,%6,%7}, {%8,%9}, {%0,%1,%2,%3};"
        : "+f"(c[0]), "+f"(c[1]), "+f"(c[2]), "+f"(c[3])
        : "r"(a[0]), "r"(a[1]), "r"(a[2]), "r"(a[3]), "r"(b[0]), "r"(b[1]));
}

// Load B-fragments of a 64x64 weight matrix for this warp's two n8-tiles,
// all 8 k-steps, split hi/lo. Held in registers for the whole GEMM.
__device__ __forceinline__ void load_wfrags(
    const float* __restrict__ W, int wn, int gid, int tg,
    uint32_t wh[2][8][2], uint32_t wl[2][8][2])
{
#pragma unroll
    for (int nt = 0; nt < 2; nt++) {
        int col = wn * 16 + nt * 8 + gid;
#pragma unroll
        for (int ks = 0; ks < 8; ks++) {
            float w0 = __ldg(W + (ks * 8 + tg) * 64 + col);
            float w1 = __ldg(W + (ks * 8 + tg + 4) * 64 + col);
            split_tf(w0, wh[nt][ks][0], wl[nt][ks][0]);
            split_tf(w1, wh[nt][ks][1], wl[nt][ks][1]);
        }
    }
}

// 3xTF32 GEMM over the CTA's 64x64 A tile (this warp: rows wm*32..+31)
__device__ __forceinline__ void gemm_3xtf32(
    const float* __restrict__ sA, int wm, int gid, int tg,
    const uint32_t wh[2][8][2], const uint32_t wl[2][8][2],
    float acc[2][2][4])
{
#pragma unroll
    for (int ks = 0; ks < 8; ks++) {
        uint32_t ah[2][4], al[2][4];
#pragma unroll
        for (int mt = 0; mt < 2; mt++) {
            int r = wm * 32 + mt * 16 + gid;
            int k = ks * 8 + tg;
            float a0 = sA[r * SAP + k];
            float a1 = sA[(r + 8) * SAP + k];
            float a2 = sA[r * SAP + k + 4];
            float a3 = sA[(r + 8) * SAP + k + 4];
            split_tf(a0, ah[mt][0], al[mt][0]);
            split_tf(a1, ah[mt][1], al[mt][1]);
            split_tf(a2, ah[mt][2], al[mt][2]);
            split_tf(a3, ah[mt][3], al[mt][3]);
        }
#pragma unroll
        for (int mt = 0; mt < 2; mt++)
#pragma unroll
            for (int nt = 0; nt < 2; nt++) {
                mma_tf32(acc[mt][nt], ah[mt], wh[nt][ks]);
                mma_tf32(acc[mt][nt], al[mt], wh[nt][ks]);
                mma_tf32(acc[mt][nt], ah[mt], wl[nt][ks]);
            }
    }
}

// ---------------------------------------------------------------------------
// Fused MLP via 3xTF32 tensor-core GEMM.
// CTA: 64 rows x 64 cols, 256 threads, warp = 32 rows x 16 cols.
// W fragments live in registers; smem holds only the A / t1 tile.
template <bool TWO>
__global__ void __launch_bounds__(256, 2) mlp_kernel(
    const float* __restrict__ A,
    const float* __restrict__ W1, const float* __restrict__ b1,
    const float* __restrict__ W2, const float* __restrict__ b2,
    float* __restrict__ out, float* __restrict__ stats, int nrows)
{
    __shared__ float sA[64 * SAP];   // 17.4 KB

    const int t = threadIdx.x;
    const int lane = t & 31, wid = t >> 5;
    const int wm = wid & 1, wn = wid >> 1;      // 2 m-warps x 4 n-warps
    const int gid = lane >> 2, tg = lane & 3;
    const int row0 = blockIdx.x * 64;

    // load A tile (64 x 64), zero-pad OOB rows
    for (int i = t; i < 1024; i += 256) {
        int r = i >> 4, k4 = (i & 15) << 2;
        float4 v = make_float4(0.f, 0.f, 0.f, 0.f);
        if (row0 + r < nrows)
            v = *(const float4*)(A + (size_t)(row0 + r) * D + k4);
        *(float4*)(sA + r * SAP + k4) = v;
    }

    uint32_t wh[2][8][2], wl[2][8][2];
    load_wfrags(W1, wn, gid, tg, wh, wl);

    float acc[2][2][4];
#pragma unroll
    for (int mt = 0; mt < 2; mt++)
#pragma unroll
        for (int nt = 0; nt < 2; nt++)
#pragma unroll
            for (int i = 0; i < 4; i++) acc[mt][nt][i] = 0.f;

    __syncthreads();
    gemm_3xtf32(sA, wm, gid, tg, wh, wl, acc);

    if (TWO) {
        __syncthreads();   // everyone done reading sA
        // t1 = relu(acc + b1) -> sA
#pragma unroll
        for (int nt = 0; nt < 2; nt++) {
            int cb = wn * 16 + nt * 8 + 2 * tg;
            float bx = __ldg(b1 + cb), by = __ldg(b1 + cb + 1);
#pragma unroll
            for (int mt = 0; mt < 2; mt++) {
                int r = wm * 32 + mt * 16 + gid;
                float2 v0 = make_float2(fmaxf(acc[mt][nt][0] + bx, 0.f),
                                        fmaxf(acc[mt][nt][1] + by, 0.f));
                float2 v1 = make_float2(fmaxf(acc[mt][nt][2] + bx, 0.f),
                                        fmaxf(acc[mt][nt][3] + by, 0.f));
                *(float2*)(sA + r * SAP + cb) = v0;
                *(float2*)(sA + (r + 8) * SAP + cb) = v1;
            }
        }
        load_wfrags(W2, wn, gid, tg, wh, wl);
#pragma unroll
        for (int mt = 0; mt < 2; mt++)
#pragma unroll
            for (int nt = 0; nt < 2; nt++)
#pragma unroll
                for (int i = 0; i < 4; i++) acc[mt][nt][i] = 0.f;
        __syncthreads();
        gemm_3xtf32(sA, wm, gid, tg, wh, wl, acc);
    }

    // epilogue: bias + relu + store + BN stats (OOB rows excluded)
    const float* bias = TWO ? b2 : b1;
    float cs[2][2] = {{0.f, 0.f}, {0.f, 0.f}};
    float cq[2][2] = {{0.f, 0.f}, {0.f, 0.f}};
#pragma unroll
    for (int nt = 0; nt < 2; nt++) {
        int cb = wn * 16 + nt * 8 + 2 * tg;
        float bx = __ldg(bias + cb), by = __ldg(bias + cb + 1);
#pragma unroll
        for (int mt = 0; mt < 2; mt++) {
#pragma unroll
            for (int h = 0; h < 2; h++) {
                int gr = row0 + wm * 32 + mt * 16 + gid + h * 8;
                if (gr < nrows) {
                    float ox = fmaxf(acc[mt][nt][2 * h + 0] + bx, 0.f);
                    float oy = fmaxf(acc[mt][nt][2 * h + 1] + by, 0.f);
                    *(float2*)(out + (size_t)gr * D + cb) = make_float2(ox, oy);
                    cs[nt][0] += ox; cq[nt][0] += ox * ox;
                    cs[nt][1] += oy; cq[nt][1] += oy * oy;
                }
            }
        }
    }
    // reduce over gid (lanes differing in bits 2..4)
#pragma unroll
    for (int off = 4; off < 32; off <<= 1) {
#pragma unroll
        for (int nt = 0; nt < 2; nt++)
#pragma unroll
            for (int j = 0; j < 2; j++) {
                cs[nt][j] += __shfl_xor_sync(0xffffffffu, cs[nt][j], off);
                cq[nt][j] += __shfl_xor_sync(0xffffffffu, cq[nt][j], off);
            }
    }
    if (gid == 0) {
#pragma unroll
        for (int nt = 0; nt < 2; nt++) {
            int c = wn * 16 + nt * 8 + 2 * tg;
            atomicAdd(stats + c,         cs[nt][0]);
            atomicAdd(stats + c + 1,     cs[nt][1]);
            atomicAdd(stats + D + c,     cq[nt][0]);
            atomicAdd(stats + D + c + 1, cq[nt][1]);
        }
    }
}

// ---------------------------------------------------------------------------
// BatchNorm apply: y = g*(x-m)*rsqrt(var+eps)+b ; writes o1 (and o2 if given)
__global__ void bn_apply_kernel(const float* __restrict__ in,
                                const float* __restrict__ stats,
                                const float* __restrict__ g,
                                const float* __restrict__ b,
                                float* __restrict__ o1, float* __restrict__ o2,
                                float invN, int total4)
{
    int i = blockIdx.x * blockDim.x + threadIdx.x;
    if (i >= total4) return;
    int c = (i << 2) & 63;
    float4 v = ((const float4*)in)[i];
    float4 y;
#pragma unroll
    for (int j = 0; j < 4; j++) {
        float m  = stats[c + j] * invN;
        float e2 = stats[D + c + j] * invN;
        float var = e2 - m * m;
        float sc = g[c + j] * rsqrtf(var + 1e-5f);
        float sh = b[c + j] - m * sc;
        float xv = (&v.x)[j];
        (&y.x)[j] = xv * sc + sh;
    }
    ((float4*)o1)[i] = y;
    if (o2) ((float4*)o2)[i] = y;
}

// ---------------------------------------------------------------------------
extern "C" void kernel_launch(void* const* d_in, const int* in_sizes, int n_in,
                              void* d_out, int out_size)
{
    const float* x      = (const float*)d_in[0];
    const int*   ei     = (const int*)d_in[1];   // int32 (JAX downcast)
    const float* W1     = (const float*)d_in[3];
    const float* b1     = (const float*)d_in[4];
    const float* W2     = (const float*)d_in[5];
    const float* b2     = (const float*)d_in[6];
    const float* bng    = (const float*)d_in[7];
    const float* bnb    = (const float*)d_in[8];
    const float* muW    = (const float*)d_in[9];
    const float* mub    = (const float*)d_in[10];
    const float* lvW    = (const float*)d_in[11];
    const float* lvb    = (const float*)d_in[12];
    const float* mug    = (const float*)d_in[13];
    const float* mubeta = (const float*)d_in[14];
    const float* lvg    = (const float*)d_in[15];
    const float* lvbeta = (const float*)d_in[16];
    float* out = (float*)d_out;

    const int n = in_sizes[0] / D;
    const int E = in_sizes[1] / 2;
    const float invN = 1.0f / (float)n;
    const int total4 = n * (D / 4);
    const int vb = (total4 + 255) / 256;
    const int gb = (n + 63) / 64;
    const int eb = (int)(((long long)E * 16 + 255) / 256);

    float *hbuf, *abuf, *tbuf, *sbuf;
    cudaGetSymbolAddress((void**)&hbuf, g_h);
    cudaGetSymbolAddress((void**)&abuf, g_agg);
    cudaGetSymbolAddress((void**)&tbuf, g_t2);
    cudaGetSymbolAddress((void**)&sbuf, g_stats);

    zero_stats_kernel<<<1, 640>>>();
    prep0_kernel<<<vb, 256>>>(x, total4);

    for (int l = 0; l < 3; l++) {
        scatter_kernel<<<eb, 256>>>(ei, E);
        mlp_kernel<true><<<gb, 256>>>(abuf,
                                      W1 + l * 4096, b1 + l * 64,
                                      W2 + l * 4096, b2 + l * 64,
                                      tbuf, sbuf + l * 128, n);
        bn_apply_kernel<<<vb, 256>>>(tbuf, sbuf + l * 128,
                                     bng + l * 64, bnb + l * 64,
                                     hbuf, abuf, invN, total4);
    }

    // mu head
    mlp_kernel<false><<<gb, 256>>>(hbuf, muW, mub, nullptr, nullptr,
                                   abuf, sbuf + 3 * 128, n);
    bn_apply_kernel<<<vb, 256>>>(abuf, sbuf + 3 * 128, mug, mubeta,
                                 out, nullptr, invN, total4);
    // logvar head
    mlp_kernel<false><<<gb, 256>>>(hbuf, lvW, lvb, nullptr, nullptr,
                                   tbuf, sbuf + 4 * 128, n);
    bn_apply_kernel<<<vb, 256>>>(tbuf, sbuf + 4 * 128, lvg, lvbeta,
                                 out + (size_t)n * D, nullptr, invN, total4);
}

// round 6
// speedup vs baseline: 4.3426x; 1.3424x over previous
#include <cuda_runtime.h>
#include <cstddef>
#include <cstdint>

#define D 64
#define NMAX 100000
#define EMAX 1300000
#define SAP 68   // smem pitch: bank = (4*gid + tg) -> conflict-free frag loads

// Scratch (no allocation allowed -> device globals)
__device__ float g_h[(size_t)NMAX * D];
__device__ float g_agg[(size_t)NMAX * D];
__device__ float g_t2[(size_t)NMAX * D];
__device__ float g_stats[5 * 2 * D];
__device__ int   g_deg[NMAX];
__device__ int   g_ptr[NMAX + 1];
__device__ int   g_cur[NMAX];
__device__ int   g_csr[EMAX];
__device__ int   g_bsum[64];

// ---------------------------------------------------------------------------
__global__ void zero_stats_kernel() {
    int i = threadIdx.x;
    if (i < 5 * 2 * D) g_stats[i] = 0.f;
}
__global__ void zero_deg_kernel(int n) {
    int i = blockIdx.x * blockDim.x + threadIdx.x;
    if (i < n) g_deg[i] = 0;
}
__global__ void hist_kernel(const int* __restrict__ ei, int E) {
    int e = blockIdx.x * blockDim.x + threadIdx.x;
    if (e < E) atomicAdd(g_deg + __ldg(ei + E + e), 1);
}

// block-level exclusive scan of g_deg -> g_ptr (2048 elems/block) + block sums
__global__ void scan1_kernel(int n) {
    __shared__ int wsum[16];
    int b = blockIdx.x, t = threadIdx.x;
    int lane = t & 31, w = t >> 5;
    int base = b * 2048 + t * 4;
    int v0 = 0, v1 = 0, v2 = 0, v3 = 0;
    if (base + 0 < n) v0 = g_deg[base + 0];
    if (base + 1 < n) v1 = g_deg[base + 1];
    if (base + 2 < n) v2 = g_deg[base + 2];
    if (base + 3 < n) v3 = g_deg[base + 3];
    int s = v0 + v1 + v2 + v3;
    int sc = s;
#pragma unroll
    for (int o = 1; o < 32; o <<= 1) {
        int x = __shfl_up_sync(0xffffffffu, sc, o);
        if (lane >= o) sc += x;
    }
    if (lane == 31) wsum[w] = sc;
    __syncthreads();
    if (w == 0) {
        int ws = (lane < 16) ? wsum[lane] : 0;
#pragma unroll
        for (int o = 1; o < 16; o <<= 1) {
            int x = __shfl_up_sync(0xffffffffu, ws, o);
            if (lane >= o) ws += x;
        }
        if (lane < 16) wsum[lane] = ws;
    }
    __syncthreads();
    int excl = sc - s + (w ? wsum[w - 1] : 0);
    if (base + 0 < n) g_ptr[base + 0] = excl;
    if (base + 1 < n) g_ptr[base + 1] = excl + v0;
    if (base + 2 < n) g_ptr[base + 2] = excl + v0 + v1;
    if (base + 3 < n) g_ptr[base + 3] = excl + v0 + v1 + v2;
    if (t == 511) g_bsum[b] = wsum[15];
}
__global__ void scan2_kernel(int nb) {
    __shared__ int sm[64];
    int t = threadIdx.x;
    sm[t] = (t < nb) ? g_bsum[t] : 0;
    __syncthreads();
    if (t == 0) {
        int run = 0;
        for (int i = 0; i < nb; i++) { int x = sm[i]; sm[i] = run; run += x; }
    }
    __syncthreads();
    if (t < nb) g_bsum[t] = sm[t];
}
__global__ void scan3_kernel(int n, int E) {
    int i = blockIdx.x * blockDim.x + threadIdx.x;
    if (i < n) {
        int p = g_ptr[i] + g_bsum[i >> 11];
        g_ptr[i] = p;
        g_cur[i] = p;
    }
    if (i == n) g_ptr[n] = E;
}
__global__ void fill_kernel(const int* __restrict__ ei, int E) {
    int e = blockIdx.x * blockDim.x + threadIdx.x;
    if (e >= E) return;
    int src = __ldg(ei + e);
    int dst = __ldg(ei + E + e);
    int pos = atomicAdd(g_cur + dst, 1);
    g_csr[pos] = src;
}

// ---------------------------------------------------------------------------
// gather: agg[i] = feat[i] + sum_{j in adj(i)} feat[src_j]; 16 lanes/node
__global__ void gather_kernel(const float* __restrict__ feat, int n) {
    int t = blockIdx.x * blockDim.x + threadIdx.x;
    int node = t >> 4;
    if (node >= n) return;
    int c = (t & 15) << 2;
    int s = __ldg(g_ptr + node), e = __ldg(g_ptr + node + 1);
    float4 acc = *(const float4*)(feat + (size_t)node * D + c);
    for (int j = s; j < e; j++) {
        int sv = __ldg(g_csr + j);
        float4 v = *(const float4*)(feat + (size_t)sv * D + c);
        acc.x += v.x; acc.y += v.y; acc.z += v.z; acc.w += v.w;
    }
    *(float4*)(g_agg + (size_t)node * D + c) = acc;
}

// ---------------------------------------------------------------------------
// tf32 helpers
__device__ __forceinline__ uint32_t f2tf(float x) {
    uint32_t r;
    asm("cvt.rna.tf32.f32 %0, %1;" : "=r"(r) : "f"(x));
    return r;
}
__device__ __forceinline__ void split_tf(float x, uint32_t& hi, uint32_t& lo) {
    hi = f2tf(x);
    lo = f2tf(x - __uint_as_float(hi));
}
__device__ __forceinline__ void mma_tf32(float* c, const uint32_t* a, const uint32_t* b) {
    asm volatile(
        "mma.sync.aligned.m16n8k8.row.col.f32.tf32.tf32.f32 "
        "{%0,%1,%2,%3}, {%4,%5,%6,%7}, {%8,%9}, {%0,%1,%2,%3};"
        : "+f"(c[0]), "+f"(c[1]), "+f"(c[2]), "+f"(c[3])
        : "r"(a[0]), "r"(a[1]), "r"(a[2]), "r"(a[3]), "r"(b[0]), "r"(b[1]));
}

__device__ __forceinline__ void load_wfrags(
    const float* __restrict__ W, int wn, int gid, int tg,
    uint32_t wh[2][8][2], uint32_t wl[2][8][2])
{
#pragma unroll
    for (int nt = 0; nt < 2; nt++) {
        int col = wn * 16 + nt * 8 + gid;
#pragma unroll
        for (int ks = 0; ks < 8; ks++) {
            float w0 = __ldg(W + (ks * 8 + tg) * 64 + col);
            float w1 = __ldg(W + (ks * 8 + tg + 4) * 64 + col);
            split_tf(w0, wh[nt][ks][0], wl[nt][ks][0]);
            split_tf(w1, wh[nt][ks][1], wl[nt][ks][1]);
        }
    }
}

// 3xTF32 GEMM using pre-split hi/lo A tiles (pure LDS + MMA mainloop)
__device__ __forceinline__ void gemm_3xtf32(
    const float* __restrict__ sAh, const float* __restrict__ sAl,
    int wm, int gid, int tg,
    const uint32_t wh[2][8][2], const uint32_t wl[2][8][2],
    float acc[2][2][4])
{
#pragma unroll
    for (int ks = 0; ks < 8; ks++) {
        uint32_t ah[2][4], al[2][4];
#pragma unroll
        for (int mt = 0; mt < 2; mt++) {
            int r = wm * 32 + mt * 16 + gid;
            int k = ks * 8 + tg;
            ah[mt][0] = __float_as_uint(sAh[r * SAP + k]);
            ah[mt][1] = __float_as_uint(sAh[(r + 8) * SAP + k]);
            ah[mt][2] = __float_as_uint(sAh[r * SAP + k + 4]);
            ah[mt][3] = __float_as_uint(sAh[(r + 8) * SAP + k + 4]);
            al[mt][0] = __float_as_uint(sAl[r * SAP + k]);
            al[mt][1] = __float_as_uint(sAl[(r + 8) * SAP + k]);
            al[mt][2] = __float_as_uint(sAl[r * SAP + k + 4]);
            al[mt][3] = __float_as_uint(sAl[(r + 8) * SAP + k + 4]);
        }
#pragma unroll
        for (int mt = 0; mt < 2; mt++)
#pragma unroll
            for (int nt = 0; nt < 2; nt++) {
                mma_tf32(acc[mt][nt], ah[mt], wh[nt][ks]);
                mma_tf32(acc[mt][nt], al[mt], wh[nt][ks]);
                mma_tf32(acc[mt][nt], ah[mt], wl[nt][ks]);
            }
    }
}

// ---------------------------------------------------------------------------
// Fused MLP via 3xTF32 tensor-core GEMM, A pre-split hi/lo in smem.
template <bool TWO>
__global__ void __launch_bounds__(256, 2) mlp_kernel(
    const float* __restrict__ A,
    const float* __restrict__ W1, const float* __restrict__ b1,
    const float* __restrict__ W2, const float* __restrict__ b2,
    float* __restrict__ out, float* __restrict__ stats, int nrows)
{
    __shared__ float sAh[64 * SAP];   // 17.4 KB
    __shared__ float sAl[64 * SAP];   // 17.4 KB

    const int t = threadIdx.x;
    const int lane = t & 31, wid = t >> 5;
    const int wm = wid & 1, wn = wid >> 1;
    const int gid = lane >> 2, tg = lane & 3;
    const int row0 = blockIdx.x * 64;

    // load A tile (64 x 64), split hi/lo during store
    for (int i = t; i < 1024; i += 256) {
        int r = i >> 4, k4 = (i & 15) << 2;
        float4 v = make_float4(0.f, 0.f, 0.f, 0.f);
        if (row0 + r < nrows)
            v = *(const float4*)(A + (size_t)(row0 + r) * D + k4);
        float4 vh, vl;
        uint32_t h_, l_;
        split_tf(v.x, h_, l_); vh.x = __uint_as_float(h_); vl.x = __uint_as_float(l_);
        split_tf(v.y, h_, l_); vh.y = __uint_as_float(h_); vl.y = __uint_as_float(l_);
        split_tf(v.z, h_, l_); vh.z = __uint_as_float(h_); vl.z = __uint_as_float(l_);
        split_tf(v.w, h_, l_); vh.w = __uint_as_float(h_); vl.w = __uint_as_float(l_);
        *(float4*)(sAh + r * SAP + k4) = vh;
        *(float4*)(sAl + r * SAP + k4) = vl;
    }

    uint32_t wh[2][8][2], wl[2][8][2];
    load_wfrags(W1, wn, gid, tg, wh, wl);

    float acc[2][2][4];
#pragma unroll
    for (int mt = 0; mt < 2; mt++)
#pragma unroll
        for (int nt = 0; nt < 2; nt++)
#pragma unroll
            for (int i = 0; i < 4; i++) acc[mt][nt][i] = 0.f;

    __syncthreads();
    gemm_3xtf32(sAh, sAl, wm, gid, tg, wh, wl, acc);

    if (TWO) {
        __syncthreads();
        // t1 = relu(acc + b1) -> split hi/lo -> sAh/sAl
#pragma unroll
        for (int nt = 0; nt < 2; nt++) {
            int cb = wn * 16 + nt * 8 + 2 * tg;
            float bx = __ldg(b1 + cb), by = __ldg(b1 + cb + 1);
#pragma unroll
            for (int mt = 0; mt < 2; mt++) {
#pragma unroll
                for (int hh = 0; hh < 2; hh++) {
                    int r = wm * 32 + mt * 16 + gid + hh * 8;
                    float ox = fmaxf(acc[mt][nt][2 * hh + 0] + bx, 0.f);
                    float oy = fmaxf(acc[mt][nt][2 * hh + 1] + by, 0.f);
                    uint32_t xh, xl, yh, yl;
                    split_tf(ox, xh, xl);
                    split_tf(oy, yh, yl);
                    *(float2*)(sAh + r * SAP + cb) =
                        make_float2(__uint_as_float(xh), __uint_as_float(yh));
                    *(float2*)(sAl + r * SAP + cb) =
                        make_float2(__uint_as_float(xl), __uint_as_float(yl));
                }
            }
        }
        load_wfrags(W2, wn, gid, tg, wh, wl);
#pragma unroll
        for (int mt = 0; mt < 2; mt++)
#pragma unroll
            for (int nt = 0; nt < 2; nt++)
#pragma unroll
                for (int i = 0; i < 4; i++) acc[mt][nt][i] = 0.f;
        __syncthreads();
        gemm_3xtf32(sAh, sAl, wm, gid, tg, wh, wl, acc);
    }

    // epilogue: bias + relu + store + BN stats
    const float* bias = TWO ? b2 : b1;
    float cs[2][2] = {{0.f, 0.f}, {0.f, 0.f}};
    float cq[2][2] = {{0.f, 0.f}, {0.f, 0.f}};
#pragma unroll
    for (int nt = 0; nt < 2; nt++) {
        int cb = wn * 16 + nt * 8 + 2 * tg;
        float bx = __ldg(bias + cb), by = __ldg(bias + cb + 1);
#pragma unroll
        for (int mt = 0; mt < 2; mt++) {
#pragma unroll
            for (int hh = 0; hh < 2; hh++) {
                int gr = row0 + wm * 32 + mt * 16 + gid + hh * 8;
                if (gr < nrows) {
                    float ox = fmaxf(acc[mt][nt][2 * hh + 0] + bx, 0.f);
                    float oy = fmaxf(acc[mt][nt][2 * hh + 1] + by, 0.f);
                    *(float2*)(out + (size_t)gr * D + cb) = make_float2(ox, oy);
                    cs[nt][0] += ox; cq[nt][0] += ox * ox;
                    cs[nt][1] += oy; cq[nt][1] += oy * oy;
                }
            }
        }
    }
#pragma unroll
    for (int off = 4; off < 32; off <<= 1) {
#pragma unroll
        for (int nt = 0; nt < 2; nt++)
#pragma unroll
            for (int j = 0; j < 2; j++) {
                cs[nt][j] += __shfl_xor_sync(0xffffffffu, cs[nt][j], off);
                cq[nt][j] += __shfl_xor_sync(0xffffffffu, cq[nt][j], off);
            }
    }
    if (gid == 0) {
#pragma unroll
        for (int nt = 0; nt < 2; nt++) {
            int c = wn * 16 + nt * 8 + 2 * tg;
            atomicAdd(stats + c,         cs[nt][0]);
            atomicAdd(stats + c + 1,     cs[nt][1]);
            atomicAdd(stats + D + c,     cq[nt][0]);
            atomicAdd(stats + D + c + 1, cq[nt][1]);
        }
    }
}

// ---------------------------------------------------------------------------
__global__ void bn_apply_kernel(const float* __restrict__ in,
                                const float* __restrict__ stats,
                                const float* __restrict__ g,
                                const float* __restrict__ b,
                                float* __restrict__ o1,
                                float invN, int total4)
{
    int i = blockIdx.x * blockDim.x + threadIdx.x;
    if (i >= total4) return;
    int c = (i << 2) & 63;
    float4 v = ((const float4*)in)[i];
    float4 y;
#pragma unroll
    for (int j = 0; j < 4; j++) {
        float m  = stats[c + j] * invN;
        float e2 = stats[D + c + j] * invN;
        float var = e2 - m * m;
        float sc = g[c + j] * rsqrtf(var + 1e-5f);
        float sh = b[c + j] - m * sc;
        float xv = (&v.x)[j];
        (&y.x)[j] = xv * sc + sh;
    }
    ((float4*)o1)[i] = y;
}

// ---------------------------------------------------------------------------
extern "C" void kernel_launch(void* const* d_in, const int* in_sizes, int n_in,
                              void* d_out, int out_size)
{
    const float* x      = (const float*)d_in[0];
    const int*   ei     = (const int*)d_in[1];   // int32 (JAX downcast)
    const float* W1     = (const float*)d_in[3];
    const float* b1     = (const float*)d_in[4];
    const float* W2     = (const float*)d_in[5];
    const float* b2     = (const float*)d_in[6];
    const float* bng    = (const float*)d_in[7];
    const float* bnb    = (const float*)d_in[8];
    const float* muW    = (const float*)d_in[9];
    const float* mub    = (const float*)d_in[10];
    const float* lvW    = (const float*)d_in[11];
    const float* lvb    = (const float*)d_in[12];
    const float* mug    = (const float*)d_in[13];
    const float* mubeta = (const float*)d_in[14];
    const float* lvg    = (const float*)d_in[15];
    const float* lvbeta = (const float*)d_in[16];
    float* out = (float*)d_out;

    const int n = in_sizes[0] / D;
    const int E = in_sizes[1] / 2;
    const float invN = 1.0f / (float)n;
    const int total4 = n * (D / 4);
    const int vb = (total4 + 255) / 256;
    const int gb = (n + 63) / 64;
    const int ebE = (E + 255) / 256;
    const int nb_scan = (n + 2047) / 2048;
    const int gatherb = (n * 16 + 255) / 256;

    float *hbuf, *abuf, *tbuf, *sbuf;
    cudaGetSymbolAddress((void**)&hbuf, g_h);
    cudaGetSymbolAddress((void**)&abuf, g_agg);
    cudaGetSymbolAddress((void**)&tbuf, g_t2);
    cudaGetSymbolAddress((void**)&sbuf, g_stats);

    zero_stats_kernel<<<1, 640>>>();

    // build CSR (dst -> list of src)
    zero_deg_kernel<<<(n + 255) / 256, 256>>>(n);
    hist_kernel<<<ebE, 256>>>(ei, E);
    scan1_kernel<<<nb_scan, 512>>>(n);
    scan2_kernel<<<1, 64>>>(nb_scan);
    scan3_kernel<<<(n + 256) / 256, 256>>>(n, E);
    fill_kernel<<<ebE, 256>>>(ei, E);

    const float* feat = x;
    for (int l = 0; l < 3; l++) {
        gather_kernel<<<gatherb, 256>>>(feat, n);
        mlp_kernel<true><<<gb, 256>>>(abuf,
                                      W1 + l * 4096, b1 + l * 64,
                                      W2 + l * 4096, b2 + l * 64,
                                      tbuf, sbuf + l * 128, n);
        bn_apply_kernel<<<vb, 256>>>(tbuf, sbuf + l * 128,
                                     bng + l * 64, bnb + l * 64,
                                     hbuf, invN, total4);
        feat = hbuf;
    }

    // mu head
    mlp_kernel<false><<<gb, 256>>>(hbuf, muW, mub, nullptr, nullptr,
                                   abuf, sbuf + 3 * 128, n);
    bn_apply_kernel<<<vb, 256>>>(abuf, sbuf + 3 * 128, mug, mubeta,
                                 out, invN, total4);
    // logvar head
    mlp_kernel<false><<<gb, 256>>>(hbuf, lvW, lvb, nullptr, nullptr,
                                   tbuf, sbuf + 4 * 128, n);
    bn_apply_kernel<<<vb, 256>>>(tbuf, sbuf + 4 * 128, lvg, lvbeta,
                                 out + (size_t)n * D, invN, total4);
}

// round 7
// speedup vs baseline: 4.5614x; 1.0504x over previous
#include <cuda_runtime.h>
#include <cuda_fp16.h>
#include <cstddef>
#include <cstdint>

#define D 64
#define NMAX 100000
#define EMAX 1300000
#define HP 36   // half2 pitch per row: bank = 4*gid + tg -> conflict-free

// Scratch (no allocation allowed -> device globals)
__device__ float g_h[(size_t)NMAX * D];
__device__ float g_agg[(size_t)NMAX * D];
__device__ float g_t2[(size_t)NMAX * D];
__device__ float g_stats[5 * 2 * D];
__device__ float g_aff[2 * D];          // BN affine (sc, sh) for fused gather
__device__ int   g_deg[NMAX];
__device__ int   g_ptr[NMAX + 1];
__device__ int   g_cur[NMAX];
__device__ int   g_csr[EMAX];
__device__ int   g_bsum[64];

// ---------------------------------------------------------------------------
__global__ void zero_kernel(int n) {
    int i = blockIdx.x * blockDim.x + threadIdx.x;
    if (i < 5 * 2 * D) g_stats[i] = 0.f;
    if (i < n) g_deg[i] = 0;
}
__global__ void hist_kernel(const int* __restrict__ ei, int E) {
    int e = blockIdx.x * blockDim.x + threadIdx.x;
    if (e < E) atomicAdd(g_deg + __ldg(ei + E + e), 1);
}
__global__ void scan1_kernel(int n) {
    __shared__ int wsum[16];
    int b = blockIdx.x, t = threadIdx.x;
    int lane = t & 31, w = t >> 5;
    int base = b * 2048 + t * 4;
    int v0 = 0, v1 = 0, v2 = 0, v3 = 0;
    if (base + 0 < n) v0 = g_deg[base + 0];
    if (base + 1 < n) v1 = g_deg[base + 1];
    if (base + 2 < n) v2 = g_deg[base + 2];
    if (base + 3 < n) v3 = g_deg[base + 3];
    int s = v0 + v1 + v2 + v3;
    int sc = s;
#pragma unroll
    for (int o = 1; o < 32; o <<= 1) {
        int x = __shfl_up_sync(0xffffffffu, sc, o);
        if (lane >= o) sc += x;
    }
    if (lane == 31) wsum[w] = sc;
    __syncthreads();
    if (w == 0) {
        int ws = (lane < 16) ? wsum[lane] : 0;
#pragma unroll
        for (int o = 1; o < 16; o <<= 1) {
            int x = __shfl_up_sync(0xffffffffu, ws, o);
            if (lane >= o) ws += x;
        }
        if (lane < 16) wsum[lane] = ws;
    }
    __syncthreads();
    int excl = sc - s + (w ? wsum[w - 1] : 0);
    if (base + 0 < n) g_ptr[base + 0] = excl;
    if (base + 1 < n) g_ptr[base + 1] = excl + v0;
    if (base + 2 < n) g_ptr[base + 2] = excl + v0 + v1;
    if (base + 3 < n) g_ptr[base + 3] = excl + v0 + v1 + v2;
    if (t == 511) g_bsum[b] = wsum[15];
}
__global__ void scan2_kernel(int nb) {
    __shared__ int sm[64];
    int t = threadIdx.x;
    sm[t] = (t < nb) ? g_bsum[t] : 0;
    __syncthreads();
    if (t == 0) {
        int run = 0;
        for (int i = 0; i < nb; i++) { int x = sm[i]; sm[i] = run; run += x; }
    }
    __syncthreads();
    if (t < nb) g_bsum[t] = sm[t];
}
__global__ void scan3_kernel(int n, int E) {
    int i = blockIdx.x * blockDim.x + threadIdx.x;
    if (i < n) {
        int p = g_ptr[i] + g_bsum[i >> 11];
        g_ptr[i] = p;
        g_cur[i] = p;
    }
    if (i == n) g_ptr[n] = E;
}
__global__ void fill_kernel(const int* __restrict__ ei, int E) {
    int e = blockIdx.x * blockDim.x + threadIdx.x;
    if (e >= E) return;
    int src = __ldg(ei + e);
    int dst = __ldg(ei + E + e);
    int pos = atomicAdd(g_cur + dst, 1);
    g_csr[pos] = src;
}

// ---------------------------------------------------------------------------
// finalize BN: stats -> affine (sc, sh) for the fused gather
__global__ void finalize_bn_kernel(const float* __restrict__ stats, 
                                   const float* __restrict__ g,
                                   const float* __restrict__ b, float invN) {
    int c = threadIdx.x;
    if (c >= D) return;
    float m  = stats[c] * invN;
    float var = stats[D + c] * invN - m * m;
    float sc = g[c] * rsqrtf(var + 1e-5f);
    g_aff[c]     = sc;
    g_aff[D + c] = b[c] - m * sc;
}

// ---------------------------------------------------------------------------
// gather (+ optional fused BN affine on the summed pre-BN features):
// agg[i] = sc * (feat[i] + sum_{j} feat[src_j]) + (1+deg)*sh
__global__ void gather_kernel(const float* __restrict__ feat, int n, int useAff) {
    int t = blockIdx.x * blockDim.x + threadIdx.x;
    int node = t >> 4;
    if (node >= n) return;
    int c = (t & 15) << 2;
    int s = __ldg(g_ptr + node), e = __ldg(g_ptr + node + 1);
    float4 acc = *(const float4*)(feat + (size_t)node * D + c);
    for (int j = s; j < e; j++) {
        int sv = __ldg(g_csr + j);
        float4 v = *(const float4*)(feat + (size_t)sv * D + c);
        acc.x += v.x; acc.y += v.y; acc.z += v.z; acc.w += v.w;
    }
    if (useAff) {
        float cnt = (float)(e - s + 1);
        float4 sc = *(const float4*)(g_aff + c);
        float4 sh = *(const float4*)(g_aff + D + c);
        acc.x = sc.x * acc.x + cnt * sh.x;
        acc.y = sc.y * acc.y + cnt * sh.y;
        acc.z = sc.z * acc.z + cnt * sh.z;
        acc.w = sc.w * acc.w + cnt * sh.w;
    }
    *(float4*)(g_agg + (size_t)node * D + c) = acc;
}

// ---------------------------------------------------------------------------
// fp16 split helpers (hi/lo, each 11-bit mantissa -> ~2^-22 combined)
__device__ __forceinline__ void split_h2(float x, float y, __half2& hi, __half2& lo) {
    __half hx = __float2half_rn(x), hy = __float2half_rn(y);
    __half lx = __float2half_rn(x - __half2float(hx));
    __half ly = __float2half_rn(y - __half2float(hy));
    hi = __halves2half2(hx, hy);
    lo = __halves2half2(lx, ly);
}
__device__ __forceinline__ void mma_f16(float* c, const uint32_t* a, const uint32_t* b) {
    asm volatile(
        "mma.sync.aligned.m16n8k16.row.col.f32.f16.f16.f32 "
        "{%0,%1,%2,%3}, {%4,%5,%6,%7}, {%8,%9}, {%0,%1,%2,%3};"
        : "+f"(c[0]), "+f"(c[1]), "+f"(c[2]), "+f"(c[3])
        : "r"(a[0]), "r"(a[1]), "r"(a[2]), "r"(a[3]), "r"(b[0]), "r"(b[1]));
}

// W fragments for m16n8k16 (col-major B, k16 x n8), split hi/lo, in registers.
// b0 packs k = 2tg,2tg+1 ; b1 packs k = 2tg+8,2tg+9 ; col = wn*16 + nt*8 + gid
__device__ __forceinline__ void load_wfrags(
    const float* __restrict__ W, int wn, int gid, int tg,
    uint32_t wh[2][4][2], uint32_t wl[2][4][2])
{
#pragma unroll
    for (int nt = 0; nt < 2; nt++) {
        int col = wn * 16 + nt * 8 + gid;
#pragma unroll
        for (int s = 0; s < 4; s++) {
            int k0 = s * 16 + 2 * tg;
            float w0 = __ldg(W + (k0 + 0) * 64 + col);
            float w1 = __ldg(W + (k0 + 1) * 64 + col);
            float w2 = __ldg(W + (k0 + 8) * 64 + col);
            float w3 = __ldg(W + (k0 + 9) * 64 + col);
            __half2 h0, l0, h1, l1;
            split_h2(w0, w1, h0, l0);
            split_h2(w2, w3, h1, l1);
            wh[nt][s][0] = *(uint32_t*)&h0; wl[nt][s][0] = *(uint32_t*)&l0;
            wh[nt][s][1] = *(uint32_t*)&h1; wl[nt][s][1] = *(uint32_t*)&l1;
        }
    }
}

// 2-way-split fp16 GEMM over the CTA's 64x64 tile (hh + hl + lh products)
__device__ __forceinline__ void gemm_f16x2(
    const uint32_t* __restrict__ sAh, const uint32_t* __restrict__ sAl,
    int wm, int gid, int tg,
    const uint32_t wh[2][4][2], const uint32_t wl[2][4][2],
    float acc[2][2][4])
{
#pragma unroll
    for (int s = 0; s < 4; s++) {
        uint32_t ah[2][4], al[2][4];
#pragma unroll
        for (int mt = 0; mt < 2; mt++) {
            int r = wm * 32 + mt * 16 + gid;
            int kb = s * 8 + tg;        // half2 index
            ah[mt][0] = sAh[r * HP + kb];
            ah[mt][1] = sAh[(r + 8) * HP + kb];
            ah[mt][2] = sAh[r * HP + kb + 4];
            ah[mt][3] = sAh[(r + 8) * HP + kb + 4];
            al[mt][0] = sAl[r * HP + kb];
            al[mt][1] = sAl[(r + 8) * HP + kb];
            al[mt][2] = sAl[r * HP + kb + 4];
            al[mt][3] = sAl[(r + 8) * HP + kb + 4];
        }
#pragma unroll
        for (int mt = 0; mt < 2; mt++)
#pragma unroll
            for (int nt = 0; nt < 2; nt++) {
                mma_f16(acc[mt][nt], ah[mt], wh[nt][s]);
                mma_f16(acc[mt][nt], al[mt], wh[nt][s]);
                mma_f16(acc[mt][nt], ah[mt], wl[nt][s]);
            }
    }
}

// ---------------------------------------------------------------------------
// Fused MLP via split-fp16 tensor-core GEMM, A pre-split hi/lo in smem.
// CTA: 64 rows x 64 cols, 256 threads (2 m-warps x 4 n-warps).
template <bool TWO>
__global__ void __launch_bounds__(256, 3) mlp_kernel(
    const float* __restrict__ A,
    const float* __restrict__ W1, const float* __restrict__ b1,
    const float* __restrict__ W2, const float* __restrict__ b2,
    float* __restrict__ out, float* __restrict__ stats, int nrows)
{
    __shared__ uint32_t sAh[64 * HP];   // 9.2 KB (half2 as u32)
    __shared__ uint32_t sAl[64 * HP];   // 9.2 KB

    const int t = threadIdx.x;
    const int lane = t & 31, wid = t >> 5;
    const int wm = wid & 1, wn = wid >> 1;
    const int gid = lane >> 2, tg = lane & 3;
    const int row0 = blockIdx.x * 64;

    // load A tile (64x64), split hi/lo into half2 during store
    for (int i = t; i < 1024; i += 256) {
        int r = i >> 4, k4 = (i & 15) << 2;
        float4 v = make_float4(0.f, 0.f, 0.f, 0.f);
        if (row0 + r < nrows)
            v = *(const float4*)(A + (size_t)(row0 + r) * D + k4);
        __half2 h0, l0, h1, l1;
        split_h2(v.x, v.y, h0, l0);
        split_h2(v.z, v.w, h1, l1);
        int idx = r * HP + (k4 >> 1);
        sAh[idx]     = *(uint32_t*)&h0;  sAl[idx]     = *(uint32_t*)&l0;
        sAh[idx + 1] = *(uint32_t*)&h1;  sAl[idx + 1] = *(uint32_t*)&l1;
    }

    uint32_t wh[2][4][2], wl[2][4][2];
    load_wfrags(W1, wn, gid, tg, wh, wl);

    float acc[2][2][4];
#pragma unroll
    for (int mt = 0; mt < 2; mt++)
#pragma unroll
        for (int nt = 0; nt < 2; nt++)
#pragma unroll
            for (int i = 0; i < 4; i++) acc[mt][nt][i] = 0.f;

    __syncthreads();
    gemm_f16x2(sAh, sAl, wm, gid, tg, wh, wl, acc);

    if (TWO) {
        __syncthreads();
        // t1 = relu(acc + b1) -> split -> sAh/sAl
        // thread owns cols cb,cb+1 at rows (gid, gid+8) per (mt,nt)
#pragma unroll
        for (int nt = 0; nt < 2; nt++) {
            int cb = wn * 16 + nt * 8 + 2 * tg;
            float bx = __ldg(b1 + cb), by = __ldg(b1 + cb + 1);
            int ci = (cb >> 1);        // half2 col index = wn*8 + nt*4 + tg
#pragma unroll
            for (int mt = 0; mt < 2; mt++) {
#pragma unroll
                for (int hh = 0; hh < 2; hh++) {
                    int r = wm * 32 + mt * 16 + gid + hh * 8;
                    float ox = fmaxf(acc[mt][nt][2 * hh + 0] + bx, 0.f);
                    float oy = fmaxf(acc[mt][nt][2 * hh + 1] + by, 0.f);
                    __half2 hi, lo;
                    split_h2(ox, oy, hi, lo);
                    sAh[r * HP + ci] = *(uint32_t*)&hi;
                    sAl[r * HP + ci] = *(uint32_t*)&lo;
                }
            }
        }
        load_wfrags(W2, wn, gid, tg, wh, wl);
#pragma unroll
        for (int mt = 0; mt < 2; mt++)
#pragma unroll
            for (int nt = 0; nt < 2; nt++)
#pragma unroll
                for (int i = 0; i < 4; i++) acc[mt][nt][i] = 0.f;
        __syncthreads();
        gemm_f16x2(sAh, sAl, wm, gid, tg, wh, wl, acc);
    }

    // epilogue: bias + relu + store + BN stats
    const float* bias = TWO ? b2 : b1;
    float cs[2][2] = {{0.f, 0.f}, {0.f, 0.f}};
    float cq[2][2] = {{0.f, 0.f}, {0.f, 0.f}};
#pragma unroll
    for (int nt = 0; nt < 2; nt++) {
        int cb = wn * 16 + nt * 8 + 2 * tg;
        float bx = __ldg(bias + cb), by = __ldg(bias + cb + 1);
#pragma unroll
        for (int mt = 0; mt < 2; mt++) {
#pragma unroll
            for (int hh = 0; hh < 2; hh++) {
                int gr = row0 + wm * 32 + mt * 16 + gid + hh * 8;
                if (gr < nrows) {
                    float ox = fmaxf(acc[mt][nt][2 * hh + 0] + bx, 0.f);
                    float oy = fmaxf(acc[mt][nt][2 * hh + 1] + by, 0.f);
                    *(float2*)(out + (size_t)gr * D + cb) = make_float2(ox, oy);
                    cs[nt][0] += ox; cq[nt][0] += ox * ox;
                    cs[nt][1] += oy; cq[nt][1] += oy * oy;
                }
            }
        }
    }
#pragma unroll
    for (int off = 4; off < 32; off <<= 1) {
#pragma unroll
        for (int nt = 0; nt < 2; nt++)
#pragma unroll
            for (int j = 0; j < 2; j++) {
                cs[nt][j] += __shfl_xor_sync(0xffffffffu, cs[nt][j], off);
                cq[nt][j] += __shfl_xor_sync(0xffffffffu, cq[nt][j], off);
            }
    }
    if (gid == 0) {
#pragma unroll
        for (int nt = 0; nt < 2; nt++) {
            int c = wn * 16 + nt * 8 + 2 * tg;
            atomicAdd(stats + c,         cs[nt][0]);
            atomicAdd(stats + c + 1,     cs[nt][1]);
            atomicAdd(stats + D + c,     cq[nt][0]);
            atomicAdd(stats + D + c + 1, cq[nt][1]);
        }
    }
}

// ---------------------------------------------------------------------------
__global__ void bn_apply_kernel(const float* __restrict__ in,
                                const float* __restrict__ stats,
                                const float* __restrict__ g,
                                const float* __restrict__ b,
                                float* __restrict__ o1,
                                float invN, int total4)
{
    int i = blockIdx.x * blockDim.x + threadIdx.x;
    if (i >= total4) return;
    int c = (i << 2) & 63;
    float4 v = ((const float4*)in)[i];
    float4 y;
#pragma unroll
    for (int j = 0; j < 4; j++) {
        float m  = stats[c + j] * invN;
        float e2 = stats[D + c + j] * invN;
        float var = e2 - m * m;
        float sc = g[c + j] * rsqrtf(var + 1e-5f);
        float sh = b[c + j] - m * sc;
        float xv = (&v.x)[j];
        (&y.x)[j] = xv * sc + sh;
    }
    ((float4*)o1)[i] = y;
}

// ---------------------------------------------------------------------------
extern "C" void kernel_launch(void* const* d_in, const int* in_sizes, int n_in,
                              void* d_out, int out_size)
{
    const float* x      = (const float*)d_in[0];
    const int*   ei     = (const int*)d_in[1];   // int32 (JAX downcast)
    const float* W1     = (const float*)d_in[3];
    const float* b1     = (const float*)d_in[4];
    const float* W2     = (const float*)d_in[5];
    const float* b2     = (const float*)d_in[6];
    const float* bng    = (const float*)d_in[7];
    const float* bnb    = (const float*)d_in[8];
    const float* muW    = (const float*)d_in[9];
    const float* mub    = (const float*)d_in[10];
    const float* lvW    = (const float*)d_in[11];
    const float* lvb    = (const float*)d_in[12];
    const float* mug    = (const float*)d_in[13];
    const float* mubeta = (const float*)d_in[14];
    const float* lvg    = (const float*)d_in[15];
    const float* lvbeta = (const float*)d_in[16];
    float* out = (float*)d_out;

    const int n = in_sizes[0] / D;
    const int E = in_sizes[1] / 2;
    const float invN = 1.0f / (float)n;
    const int total4 = n * (D / 4);
    const int vb = (total4 + 255) / 256;
    const int gb = (n + 63) / 64;
    const int ebE = (E + 255) / 256;
    const int nb_scan = (n + 2047) / 2048;
    const int gatherb = (n * 16 + 255) / 256;

    float *hbuf, *abuf, *tbuf, *sbuf;
    cudaGetSymbolAddress((void**)&hbuf, g_h);
    cudaGetSymbolAddress((void**)&abuf, g_agg);
    cudaGetSymbolAddress((void**)&tbuf, g_t2);
    cudaGetSymbolAddress((void**)&sbuf, g_stats);

    zero_kernel<<<(n + 255) / 256, 256>>>(n);

    // build CSR (dst -> list of src)
    hist_kernel<<<ebE, 256>>>(ei, E);
    scan1_kernel<<<nb_scan, 512>>>(n);
    scan2_kernel<<<1, 64>>>(nb_scan);
    scan3_kernel<<<(n + 256) / 256, 256>>>(n, E);
    fill_kernel<<<ebE, 256>>>(ei, E);

    // layer 1 (input x, no BN affine)
    gather_kernel<<<gatherb, 256>>>(x, n, 0);
    mlp_kernel<true><<<gb, 256>>>(abuf, W1, b1, W2, b2, tbuf, sbuf, n);

    // layer 2 (gather reads pre-BN t2, applies layer-1 BN affine inline)
    finalize_bn_kernel<<<1, 64>>>(sbuf, bng, bnb, invN);
    gather_kernel<<<gatherb, 256>>>(tbuf, n, 1);
    mlp_kernel<true><<<gb, 256>>>(abuf, W1 + 4096, b1 + 64, W2 + 4096, b2 + 64,
                                  tbuf, sbuf + 128, n);

    // layer 3
    finalize_bn_kernel<<<1, 64>>>(sbuf + 128, bng + 64, bnb + 64, invN);
    gather_kernel<<<gatherb, 256>>>(tbuf, n, 1);
    mlp_kernel<true><<<gb, 256>>>(abuf, W1 + 8192, b1 + 128, W2 + 8192, b2 + 128,
                                  tbuf, sbuf + 256, n);
    // h3 = BN(t2) explicitly (heads need it densely)
    bn_apply_kernel<<<vb, 256>>>(tbuf, sbuf + 256, bng + 128, bnb + 128,
                                 hbuf, invN, total4);

    // mu head
    mlp_kernel<false><<<gb, 256>>>(hbuf, muW, mub, nullptr, nullptr,
                                   abuf, sbuf + 3 * 128, n);
    bn_apply_kernel<<<vb, 256>>>(abuf, sbuf + 3 * 128, mug, mubeta,
                                 out, invN, total4);
    // logvar head
    mlp_kernel<false><<<gb, 256>>>(hbuf, lvW, lvb, nullptr, nullptr,
                                   tbuf, sbuf + 4 * 128, n);
    bn_apply_kernel<<<vb, 256>>>(tbuf, sbuf + 4 * 128, lvg, lvbeta,
                                 out + (size_t)n * D, invN, total4);
}

// round 10
// speedup vs baseline: 4.8564x; 1.0647x over previous
#include <cuda_runtime.h>
#include <cuda_fp16.h>
#include <cstddef>
#include <cstdint>

#define D 64
#define NMAX 100000
#define EMAX 1300000
#define HP 36   // half2 pitch per row: bank = 4*gid + tg -> conflict-free

// Scratch (no allocation allowed -> device globals)
__device__ float  g_h[(size_t)NMAX * D];
__device__ float  g_t2[(size_t)NMAX * D];
__device__ float  g_stats[5 * 2 * D];
__device__ int    g_deg[NMAX];
__device__ int    g_ptr[NMAX + 1];
__device__ int    g_cur[NMAX];
__device__ int    g_csr[EMAX];
__device__ int    g_bsum[64];

// ---------------------------------------------------------------------------
__global__ void zero_kernel(int n) {
    int i = blockIdx.x * blockDim.x + threadIdx.x;
    if (i < 5 * 2 * D) g_stats[i] = 0.f;
    if (i < n) g_deg[i] = 0;
}
__global__ void hist_kernel(const int* __restrict__ ei, int E) {
    int e = blockIdx.x * blockDim.x + threadIdx.x;
    if (e < E) atomicAdd(g_deg + __ldg(ei + E + e), 1);
}
__global__ void scan1_kernel(int n) {
    __shared__ int wsum[16];
    int b = blockIdx.x, t = threadIdx.x;
    int lane = t & 31, w = t >> 5;
    int base = b * 2048 + t * 4;
    int v0 = 0, v1 = 0, v2 = 0, v3 = 0;
    if (base + 0 < n) v0 = g_deg[base + 0];
    if (base + 1 < n) v1 = g_deg[base + 1];
    if (base + 2 < n) v2 = g_deg[base + 2];
    if (base + 3 < n) v3 = g_deg[base + 3];
    int s = v0 + v1 + v2 + v3;
    int sc = s;
#pragma unroll
    for (int o = 1; o < 32; o <<= 1) {
        int x = __shfl_up_sync(0xffffffffu, sc, o);
        if (lane >= o) sc += x;
    }
    if (lane == 31) wsum[w] = sc;
    __syncthreads();
    if (w == 0) {
        int ws = (lane < 16) ? wsum[lane] : 0;
#pragma unroll
        for (int o = 1; o < 16; o <<= 1) {
            int x = __shfl_up_sync(0xffffffffu, ws, o);
            if (lane >= o) ws += x;
        }
        if (lane < 16) wsum[lane] = ws;
    }
    __syncthreads();
    int excl = sc - s + (w ? wsum[w - 1] : 0);
    if (base + 0 < n) g_ptr[base + 0] = excl;
    if (base + 1 < n) g_ptr[base + 1] = excl + v0;
    if (base + 2 < n) g_ptr[base + 2] = excl + v0 + v1;
    if (base + 3 < n) g_ptr[base + 3] = excl + v0 + v1 + v2;
    if (t == 511) g_bsum[b] = wsum[15];
}
__global__ void scan2_kernel(int nb) {
    __shared__ int sm[64];
    int t = threadIdx.x;
    sm[t] = (t < nb) ? g_bsum[t] : 0;
    __syncthreads();
    if (t == 0) {
        int run = 0;
        for (int i = 0; i < nb; i++) { int x = sm[i]; sm[i] = run; run += x; }
    }
    __syncthreads();
    if (t < nb) g_bsum[t] = sm[t];
}
__global__ void scan3_kernel(int n, int E) {
    int i = blockIdx.x * blockDim.x + threadIdx.x;
    if (i < n) {
        int p = g_ptr[i] + g_bsum[i >> 11];
        g_ptr[i] = p;
        g_cur[i] = p;
    }
    if (i == n) g_ptr[n] = E;
}
__global__ void fill_kernel(const int* __restrict__ ei, int E) {
    int e = blockIdx.x * blockDim.x + threadIdx.x;
    if (e >= E) return;
    int src = __ldg(ei + e);
    int dst = __ldg(ei + E + e);
    int pos = atomicAdd(g_cur + dst, 1);
    g_csr[pos] = src;
}

// ---------------------------------------------------------------------------
// fp16 split helpers (hi/lo -> ~2^-22 combined mantissa)
__device__ __forceinline__ void split_h2(float x, float y, uint32_t& hi, uint32_t& lo) {
    __half hx = __float2half_rn(x), hy = __float2half_rn(y);
    __half lx = __float2half_rn(x - __half2float(hx));
    __half ly = __float2half_rn(y - __half2float(hy));
    __half2 h = __halves2half2(hx, hy), l = __halves2half2(lx, ly);
    hi = *(uint32_t*)&h; lo = *(uint32_t*)&l;
}
__device__ __forceinline__ void mma_f16(float* c, const uint32_t* a, const uint32_t* b) {
    asm volatile(
        "mma.sync.aligned.m16n8k16.row.col.f32.f16.f16.f32 "
        "{%0,%1,%2,%3}, {%4,%5,%6,%7}, {%8,%9}, {%0,%1,%2,%3};"
        : "+f"(c[0]), "+f"(c[1]), "+f"(c[2]), "+f"(c[3])
        : "r"(a[0]), "r"(a[1]), "r"(a[2]), "r"(a[3]), "r"(b[0]), "r"(b[1]));
}

__device__ __forceinline__ void load_wfrags(
    const float* __restrict__ W, int wn, int gid, int tg,
    uint32_t wh[2][4][2], uint32_t wl[2][4][2])
{
#pragma unroll
    for (int nt = 0; nt < 2; nt++) {
        int col = wn * 16 + nt * 8 + gid;
#pragma unroll
        for (int s = 0; s < 4; s++) {
            int k0 = s * 16 + 2 * tg;
            float w0 = __ldg(W + (k0 + 0) * 64 + col);
            float w1 = __ldg(W + (k0 + 1) * 64 + col);
            float w2 = __ldg(W + (k0 + 8) * 64 + col);
            float w3 = __ldg(W + (k0 + 9) * 64 + col);
            split_h2(w0, w1, wh[nt][s][0], wl[nt][s][0]);
            split_h2(w2, w3, wh[nt][s][1], wl[nt][s][1]);
        }
    }
}

__device__ __forceinline__ void gemm_f16x2(
    const uint32_t* __restrict__ sAh, const uint32_t* __restrict__ sAl,
    int wm, int gid, int tg,
    const uint32_t wh[2][4][2], const uint32_t wl[2][4][2],
    float acc[2][2][4])
{
#pragma unroll
    for (int s = 0; s < 4; s++) {
        uint32_t ah[2][4], al[2][4];
#pragma unroll
        for (int mt = 0; mt < 2; mt++) {
            int r = wm * 32 + mt * 16 + gid;
            int kb = s * 8 + tg;
            ah[mt][0] = sAh[r * HP + kb];
            ah[mt][1] = sAh[(r + 8) * HP + kb];
            ah[mt][2] = sAh[r * HP + kb + 4];
            ah[mt][3] = sAh[(r + 8) * HP + kb + 4];
            al[mt][0] = sAl[r * HP + kb];
            al[mt][1] = sAl[(r + 8) * HP + kb];
            al[mt][2] = sAl[r * HP + kb + 4];
            al[mt][3] = sAl[(r + 8) * HP + kb + 4];
        }
#pragma unroll
        for (int mt = 0; mt < 2; mt++)
#pragma unroll
            for (int nt = 0; nt < 2; nt++) {
                mma_f16(acc[mt][nt], ah[mt], wh[nt][s]);
                mma_f16(acc[mt][nt], al[mt], wh[nt][s]);
                mma_f16(acc[mt][nt], ah[mt], wl[nt][s]);
            }
    }
}

// ---------------------------------------------------------------------------
// Fused [gather +] MLP via split-fp16 tensor-core GEMM.
// GATHER: false = dense fp32 tile load, true = CSR-gather (fp32 features)
//         with optional fused BN affine (pstats != nullptr).
template <bool TWO, bool GATHER>
__global__ void __launch_bounds__(256, 3) mlp_kernel(
    const float* __restrict__ feat,
    const float* __restrict__ pstats, const float* __restrict__ pg,
    const float* __restrict__ pb,
    const float* __restrict__ W1, const float* __restrict__ b1,
    const float* __restrict__ W2, const float* __restrict__ b2,
    float* __restrict__ outF,
    float* __restrict__ stats, float invN, int nrows)
{
    __shared__ uint32_t sAh[64 * HP];   // 9.2 KB
    __shared__ uint32_t sAl[64 * HP];   // 9.2 KB
    __shared__ float    sAff[2 * D];

    const int t = threadIdx.x;
    const int lane = t & 31, wid = t >> 5;
    const int wm = wid & 1, wn = wid >> 1;
    const int gid = lane >> 2, tg = lane & 3;
    const int row0 = blockIdx.x * 64;
    const bool useAff = GATHER && (pstats != nullptr);

    if (useAff && t < D) {
        float m  = pstats[t] * invN;
        float var = pstats[D + t] * invN - m * m;
        float sc = pg[t] * rsqrtf(var + 1e-5f);
        sAff[t]     = sc;
        sAff[D + t] = pb[t] - m * sc;
    }
    if (useAff) __syncthreads();

    if (!GATHER) {
        // dense fp32 tile load
        for (int i = t; i < 1024; i += 256) {
            int r = i >> 4, k4 = (i & 15) << 2;
            float4 v = make_float4(0.f, 0.f, 0.f, 0.f);
            if (row0 + r < nrows)
                v = *(const float4*)(feat + (size_t)(row0 + r) * D + k4);
            int idx = r * HP + (k4 >> 1);
            split_h2(v.x, v.y, sAh[idx], sAl[idx]);
            split_h2(v.z, v.w, sAh[idx + 1], sAl[idx + 1]);
        }
    } else {
        // fused CSR gather from fp32 features, 16 lanes/node
#pragma unroll
        for (int pass = 0; pass < 4; pass++) {
            int r = pass * 16 + (t >> 4);
            int node = row0 + r;
            int c4 = (t & 15) << 2;
            float4 acc = make_float4(0.f, 0.f, 0.f, 0.f);
            if (node < nrows) {
                acc = *(const float4*)(feat + (size_t)node * D + c4);
                int s = __ldg(g_ptr + node), e = __ldg(g_ptr + node + 1);
                for (int j = s; j < e; j++) {
                    int sv = __ldg(g_csr + j);
                    float4 v = *(const float4*)(feat + (size_t)sv * D + c4);
                    acc.x += v.x; acc.y += v.y; acc.z += v.z; acc.w += v.w;
                }
                if (useAff) {
                    float cnt = (float)(e - s + 1);
                    acc.x = sAff[c4 + 0] * acc.x + cnt * sAff[D + c4 + 0];
                    acc.y = sAff[c4 + 1] * acc.y + cnt * sAff[D + c4 + 1];
                    acc.z = sAff[c4 + 2] * acc.z + cnt * sAff[D + c4 + 2];
                    acc.w = sAff[c4 + 3] * acc.w + cnt * sAff[D + c4 + 3];
                }
            }
            int idx = r * HP + (c4 >> 1);
            split_h2(acc.x, acc.y, sAh[idx], sAl[idx]);
            split_h2(acc.z, acc.w, sAh[idx + 1], sAl[idx + 1]);
        }
    }

    uint32_t wh[2][4][2], wl[2][4][2];
    load_wfrags(W1, wn, gid, tg, wh, wl);

    float acc[2][2][4];
#pragma unroll
    for (int mt = 0; mt < 2; mt++)
#pragma unroll
        for (int nt = 0; nt < 2; nt++)
#pragma unroll
            for (int i = 0; i < 4; i++) acc[mt][nt][i] = 0.f;

    __syncthreads();
    gemm_f16x2(sAh, sAl, wm, gid, tg, wh, wl, acc);

    if (TWO) {
        __syncthreads();
#pragma unroll
        for (int nt = 0; nt < 2; nt++) {
            int cb = wn * 16 + nt * 8 + 2 * tg;
            float bx = __ldg(b1 + cb), by = __ldg(b1 + cb + 1);
            int ci = (cb >> 1);
#pragma unroll
            for (int mt = 0; mt < 2; mt++) {
#pragma unroll
                for (int hh = 0; hh < 2; hh++) {
                    int r = wm * 32 + mt * 16 + gid + hh * 8;
                    float ox = fmaxf(acc[mt][nt][2 * hh + 0] + bx, 0.f);
                    float oy = fmaxf(acc[mt][nt][2 * hh + 1] + by, 0.f);
                    split_h2(ox, oy, sAh[r * HP + ci], sAl[r * HP + ci]);
                }
            }
        }
        load_wfrags(W2, wn, gid, tg, wh, wl);
#pragma unroll
        for (int mt = 0; mt < 2; mt++)
#pragma unroll
            for (int nt = 0; nt < 2; nt++)
#pragma unroll
                for (int i = 0; i < 4; i++) acc[mt][nt][i] = 0.f;
        __syncthreads();
        gemm_f16x2(sAh, sAl, wm, gid, tg, wh, wl, acc);
    }

    // epilogue: bias + relu + store + BN stats
    const float* bias = TWO ? b2 : b1;
    float cs[2][2] = {{0.f, 0.f}, {0.f, 0.f}};
    float cq[2][2] = {{0.f, 0.f}, {0.f, 0.f}};
#pragma unroll
    for (int nt = 0; nt < 2; nt++) {
        int cb = wn * 16 + nt * 8 + 2 * tg;
        float bx = __ldg(bias + cb), by = __ldg(bias + cb + 1);
#pragma unroll
        for (int mt = 0; mt < 2; mt++) {
#pragma unroll
            for (int hh = 0; hh < 2; hh++) {
                int gr = row0 + wm * 32 + mt * 16 + gid + hh * 8;
                if (gr < nrows) {
                    float ox = fmaxf(acc[mt][nt][2 * hh + 0] + bx, 0.f);
                    float oy = fmaxf(acc[mt][nt][2 * hh + 1] + by, 0.f);
                    *(float2*)(outF + (size_t)gr * D + cb) = make_float2(ox, oy);
                    cs[nt][0] += ox; cq[nt][0] += ox * ox;
                    cs[nt][1] += oy; cq[nt][1] += oy * oy;
                }
            }
        }
    }
#pragma unroll
    for (int off = 4; off < 32; off <<= 1) {
#pragma unroll
        for (int nt = 0; nt < 2; nt++)
#pragma unroll
            for (int j = 0; j < 2; j++) {
                cs[nt][j] += __shfl_xor_sync(0xffffffffu, cs[nt][j], off);
                cq[nt][j] += __shfl_xor_sync(0xffffffffu, cq[nt][j], off);
            }
    }
    if (gid == 0) {
#pragma unroll
        for (int nt = 0; nt < 2; nt++) {
            int c = wn * 16 + nt * 8 + 2 * tg;
            atomicAdd(stats + c,         cs[nt][0]);
            atomicAdd(stats + c + 1,     cs[nt][1]);
            atomicAdd(stats + D + c,     cq[nt][0]);
            atomicAdd(stats + D + c + 1, cq[nt][1]);
        }
    }
}

// ---------------------------------------------------------------------------
__global__ void bn_apply_kernel(const float* __restrict__ in,
                                const float* __restrict__ stats,
                                const float* __restrict__ g,
                                const float* __restrict__ b,
                                float* __restrict__ o1,
                                float invN, int total4)
{
    int i = blockIdx.x * blockDim.x + threadIdx.x;
    if (i >= total4) return;
    int c = (i << 2) & 63;
    float4 v = ((const float4*)in)[i];
    float4 y;
#pragma unroll
    for (int j = 0; j < 4; j++) {
        float m  = stats[c + j] * invN;
        float e2 = stats[D + c + j] * invN;
        float var = e2 - m * m;
        float sc = g[c + j] * rsqrtf(var + 1e-5f);
        float sh = b[c + j] - m * sc;
        float xv = (&v.x)[j];
        (&y.x)[j] = xv * sc + sh;
    }
    ((float4*)o1)[i] = y;
}

// ---------------------------------------------------------------------------
extern "C" void kernel_launch(void* const* d_in, const int* in_sizes, int n_in,
                              void* d_out, int out_size)
{
    const float* x      = (const float*)d_in[0];
    const int*   ei     = (const int*)d_in[1];   // int32 (JAX downcast)
    const float* W1     = (const float*)d_in[3];
    const float* b1     = (const float*)d_in[4];
    const float* W2     = (const float*)d_in[5];
    const float* b2     = (const float*)d_in[6];
    const float* bng    = (const float*)d_in[7];
    const float* bnb    = (const float*)d_in[8];
    const float* muW    = (const float*)d_in[9];
    const float* mub    = (const float*)d_in[10];
    const float* lvW    = (const float*)d_in[11];
    const float* lvb    = (const float*)d_in[12];
    const float* mug    = (const float*)d_in[13];
    const float* mubeta = (const float*)d_in[14];
    const float* lvg    = (const float*)d_in[15];
    const float* lvbeta = (const float*)d_in[16];
    float* out = (float*)d_out;

    const int n = in_sizes[0] / D;
    const int E = in_sizes[1] / 2;
    const float invN = 1.0f / (float)n;
    const int total4 = n * (D / 4);
    const int vb = (total4 + 255) / 256;
    const int gb = (n + 63) / 64;
    const int ebE = (E + 255) / 256;
    const int nb_scan = (n + 2047) / 2048;

    float *hbuf, *tbuf, *sbuf;
    cudaGetSymbolAddress((void**)&hbuf, g_h);
    cudaGetSymbolAddress((void**)&tbuf, g_t2);
    cudaGetSymbolAddress((void**)&sbuf, g_stats);

    zero_kernel<<<(n + 255) / 256, 256>>>(n);

    // build CSR (dst -> list of src)
    hist_kernel<<<ebE, 256>>>(ei, E);
    scan1_kernel<<<nb_scan, 512>>>(n);
    scan2_kernel<<<1, 64>>>(nb_scan);
    scan3_kernel<<<(n + 256) / 256, 256>>>(n, E);
    fill_kernel<<<ebE, 256>>>(ei, E);

    // layer 1: gather x, no affine -> t2 (pre-BN, fp32)
    mlp_kernel<true, true><<<gb, 256>>>(
        x, nullptr, nullptr, nullptr,
        W1, b1, W2, b2, tbuf, sbuf, invN, n);
    // layer 2: gather t2 + layer-1 affine -> h
    mlp_kernel<true, true><<<gb, 256>>>(
        tbuf, sbuf, bng, bnb,
        W1 + 4096, b1 + 64, W2 + 4096, b2 + 64, hbuf, sbuf + 128, invN, n);
    // layer 3: gather h + layer-2 affine -> t2
    mlp_kernel<true, true><<<gb, 256>>>(
        hbuf, sbuf + 128, bng + 64, bnb + 64,
        W1 + 8192, b1 + 128, W2 + 8192, b2 + 128, tbuf, sbuf + 256, invN, n);
    // h3 = BN(t2) -> h
    bn_apply_kernel<<<vb, 256>>>(tbuf, sbuf + 256, bng + 128, bnb + 128,
                                 hbuf, invN, total4);

    // mu head (dense fp32 in, stage in t2)
    mlp_kernel<false, false><<<gb, 256>>>(
        hbuf, nullptr, nullptr, nullptr,
        muW, mub, nullptr, nullptr, tbuf, sbuf + 3 * 128, invN, n);
    bn_apply_kernel<<<vb, 256>>>(tbuf, sbuf + 3 * 128, mug, mubeta,
                                 out, invN, total4);
    // logvar head
    mlp_kernel<false, false><<<gb, 256>>>(
        hbuf, nullptr, nullptr, nullptr,
        lvW, lvb, nullptr, nullptr, tbuf, sbuf + 4 * 128, invN, n);
    bn_apply_kernel<<<vb, 256>>>(tbuf, sbuf + 4 * 128, lvg, lvbeta,
                                 out + (size_t)n * D, invN, total4);
}

// round 11
// speedup vs baseline: 5.4139x; 1.1148x over previous
#include <cuda_runtime.h>
#include <cuda_fp16.h>
#include <cstddef>
#include <cstdint>

#define D 64
#define NMAX 100000
#define EMAX 1300000
#define HP 36   // half2 pitch per row: bank = 4*gid + tg -> conflict-free

// Scratch (no allocation allowed -> device globals)
__device__ float  g_h[(size_t)NMAX * D];
__device__ float  g_t2[(size_t)NMAX * D];
__device__ float  g_stats[5 * 2 * D];
__device__ int    g_deg[NMAX];
__device__ int    g_ptr[NMAX + 1];
__device__ int    g_cur[NMAX];
__device__ int    g_csr[EMAX];
__device__ int    g_bsum[64];

// ---------------------------------------------------------------------------
__global__ void zero_kernel(int n) {
    int i = blockIdx.x * blockDim.x + threadIdx.x;
    if (i < 5 * 2 * D) g_stats[i] = 0.f;
    if (i < n) g_deg[i] = 0;
}
__global__ void hist_kernel(const int* __restrict__ ei, int E) {
    int e = blockIdx.x * blockDim.x + threadIdx.x;
    if (e < E) atomicAdd(g_deg + __ldg(ei + E + e), 1);
}
__global__ void scan1_kernel(int n) {
    __shared__ int wsum[16];
    int b = blockIdx.x, t = threadIdx.x;
    int lane = t & 31, w = t >> 5;
    int base = b * 2048 + t * 4;
    int v0 = 0, v1 = 0, v2 = 0, v3 = 0;
    if (base + 0 < n) v0 = g_deg[base + 0];
    if (base + 1 < n) v1 = g_deg[base + 1];
    if (base + 2 < n) v2 = g_deg[base + 2];
    if (base + 3 < n) v3 = g_deg[base + 3];
    int s = v0 + v1 + v2 + v3;
    int sc = s;
#pragma unroll
    for (int o = 1; o < 32; o <<= 1) {
        int x = __shfl_up_sync(0xffffffffu, sc, o);
        if (lane >= o) sc += x;
    }
    if (lane == 31) wsum[w] = sc;
    __syncthreads();
    if (w == 0) {
        int ws = (lane < 16) ? wsum[lane] : 0;
#pragma unroll
        for (int o = 1; o < 16; o <<= 1) {
            int x = __shfl_up_sync(0xffffffffu, ws, o);
            if (lane >= o) ws += x;
        }
        if (lane < 16) wsum[lane] = ws;
    }
    __syncthreads();
    int excl = sc - s + (w ? wsum[w - 1] : 0);
    if (base + 0 < n) g_ptr[base + 0] = excl;
    if (base + 1 < n) g_ptr[base + 1] = excl + v0;
    if (base + 2 < n) g_ptr[base + 2] = excl + v0 + v1;
    if (base + 3 < n) g_ptr[base + 3] = excl + v0 + v1 + v2;
    if (t == 511) g_bsum[b] = wsum[15];
}
__global__ void scan2_kernel(int nb) {
    __shared__ int sm[64];
    int t = threadIdx.x;
    sm[t] = (t < nb) ? g_bsum[t] : 0;
    __syncthreads();
    if (t == 0) {
        int run = 0;
        for (int i = 0; i < nb; i++) { int x = sm[i]; sm[i] = run; run += x; }
    }
    __syncthreads();
    if (t < nb) g_bsum[t] = sm[t];
}
__global__ void scan3_kernel(int n, int E) {
    int i = blockIdx.x * blockDim.x + threadIdx.x;
    if (i < n) {
        int p = g_ptr[i] + g_bsum[i >> 11];
        g_ptr[i] = p;
        g_cur[i] = p;
    }
    if (i == n) g_ptr[n] = E;
}
__global__ void fill_kernel(const int* __restrict__ ei, int E) {
    int e = blockIdx.x * blockDim.x + threadIdx.x;
    if (e >= E) return;
    int src = __ldg(ei + e);
    int dst = __ldg(ei + E + e);
    int pos = atomicAdd(g_cur + dst, 1);
    g_csr[pos] = src;
}

// ---------------------------------------------------------------------------
// fp16 split helpers (hi/lo -> ~2^-22 combined mantissa)
__device__ __forceinline__ void split_h2(float x, float y, uint32_t& hi, uint32_t& lo) {
    __half hx = __float2half_rn(x), hy = __float2half_rn(y);
    __half lx = __float2half_rn(x - __half2float(hx));
    __half ly = __float2half_rn(y - __half2float(hy));
    __half2 h = __halves2half2(hx, hy), l = __halves2half2(lx, ly);
    hi = *(uint32_t*)&h; lo = *(uint32_t*)&l;
}
__device__ __forceinline__ void mma_f16(float* c, const uint32_t* a, const uint32_t* b) {
    asm volatile(
        "mma.sync.aligned.m16n8k16.row.col.f32.f16.f16.f32 "
        "{%0,%1,%2,%3}, {%4,%5,%6,%7}, {%8,%9}, {%0,%1,%2,%3};"
        : "+f"(c[0]), "+f"(c[1]), "+f"(c[2]), "+f"(c[3])
        : "r"(a[0]), "r"(a[1]), "r"(a[2]), "r"(a[3]), "r"(b[0]), "r"(b[1]));
}

__device__ __forceinline__ void load_wfrags(
    const float* __restrict__ W, int wn, int gid, int tg,
    uint32_t wh[2][4][2], uint32_t wl[2][4][2])
{
#pragma unroll
    for (int nt = 0; nt < 2; nt++) {
        int col = wn * 16 + nt * 8 + gid;
#pragma unroll
        for (int s = 0; s < 4; s++) {
            int k0 = s * 16 + 2 * tg;
            float w0 = __ldg(W + (k0 + 0) * 64 + col);
            float w1 = __ldg(W + (k0 + 1) * 64 + col);
            float w2 = __ldg(W + (k0 + 8) * 64 + col);
            float w3 = __ldg(W + (k0 + 9) * 64 + col);
            split_h2(w0, w1, wh[nt][s][0], wl[nt][s][0]);
            split_h2(w2, w3, wh[nt][s][1], wl[nt][s][1]);
        }
    }
}

__device__ __forceinline__ void gemm_f16x2(
    const uint32_t* __restrict__ sAh, const uint32_t* __restrict__ sAl,
    int wm, int gid, int tg,
    const uint32_t wh[2][4][2], const uint32_t wl[2][4][2],
    float acc[2][2][4])
{
#pragma unroll
    for (int s = 0; s < 4; s++) {
        uint32_t ah[2][4], al[2][4];
#pragma unroll
        for (int mt = 0; mt < 2; mt++) {
            int r = wm * 32 + mt * 16 + gid;
            int kb = s * 8 + tg;
            ah[mt][0] = sAh[r * HP + kb];
            ah[mt][1] = sAh[(r + 8) * HP + kb];
            ah[mt][2] = sAh[r * HP + kb + 4];
            ah[mt][3] = sAh[(r + 8) * HP + kb + 4];
            al[mt][0] = sAl[r * HP + kb];
            al[mt][1] = sAl[(r + 8) * HP + kb];
            al[mt][2] = sAl[r * HP + kb + 4];
            al[mt][3] = sAl[(r + 8) * HP + kb + 4];
        }
#pragma unroll
        for (int mt = 0; mt < 2; mt++)
#pragma unroll
            for (int nt = 0; nt < 2; nt++) {
                mma_f16(acc[mt][nt], ah[mt], wh[nt][s]);
                mma_f16(acc[mt][nt], al[mt], wh[nt][s]);
                mma_f16(acc[mt][nt], ah[mt], wl[nt][s]);
            }
    }
}

// shared epilogue: bias + relu + store + BN-stat atomics
__device__ __forceinline__ void epilogue(
    float acc[2][2][4], const float* __restrict__ bias,
    float* __restrict__ outF, float* __restrict__ stats,
    int row0, int wm, int wn, int gid, int tg, int nrows)
{
    float cs[2][2] = {{0.f, 0.f}, {0.f, 0.f}};
    float cq[2][2] = {{0.f, 0.f}, {0.f, 0.f}};
#pragma unroll
    for (int nt = 0; nt < 2; nt++) {
        int cb = wn * 16 + nt * 8 + 2 * tg;
        float bx = __ldg(bias + cb), by = __ldg(bias + cb + 1);
#pragma unroll
        for (int mt = 0; mt < 2; mt++) {
#pragma unroll
            for (int hh = 0; hh < 2; hh++) {
                int gr = row0 + wm * 32 + mt * 16 + gid + hh * 8;
                if (gr < nrows) {
                    float ox = fmaxf(acc[mt][nt][2 * hh + 0] + bx, 0.f);
                    float oy = fmaxf(acc[mt][nt][2 * hh + 1] + by, 0.f);
                    *(float2*)(outF + (size_t)gr * D + cb) = make_float2(ox, oy);
                    cs[nt][0] += ox; cq[nt][0] += ox * ox;
                    cs[nt][1] += oy; cq[nt][1] += oy * oy;
                }
            }
        }
    }
#pragma unroll
    for (int off = 4; off < 32; off <<= 1) {
#pragma unroll
        for (int nt = 0; nt < 2; nt++)
#pragma unroll
            for (int j = 0; j < 2; j++) {
                cs[nt][j] += __shfl_xor_sync(0xffffffffu, cs[nt][j], off);
                cq[nt][j] += __shfl_xor_sync(0xffffffffu, cq[nt][j], off);
            }
    }
    if (gid == 0) {
#pragma unroll
        for (int nt = 0; nt < 2; nt++) {
            int c = wn * 16 + nt * 8 + 2 * tg;
            atomicAdd(stats + c,         cs[nt][0]);
            atomicAdd(stats + c + 1,     cs[nt][1]);
            atomicAdd(stats + D + c,     cq[nt][0]);
            atomicAdd(stats + D + c + 1, cq[nt][1]);
        }
    }
}

// ---------------------------------------------------------------------------
// Fused gather + 2-layer MLP via split-fp16 tensor-core GEMM.
// CSR-gather from fp32 features with optional fused BN affine.
__global__ void __launch_bounds__(256, 3) mlp_kernel(
    const float* __restrict__ feat,
    const float* __restrict__ pstats, const float* __restrict__ pg,
    const float* __restrict__ pb,
    const float* __restrict__ W1, const float* __restrict__ b1,
    const float* __restrict__ W2, const float* __restrict__ b2,
    float* __restrict__ outF,
    float* __restrict__ stats, float invN, int nrows)
{
    __shared__ uint32_t sAh[64 * HP];
    __shared__ uint32_t sAl[64 * HP];
    __shared__ float    sAff[2 * D];

    const int t = threadIdx.x;
    const int lane = t & 31, wid = t >> 5;
    const int wm = wid & 1, wn = wid >> 1;
    const int gid = lane >> 2, tg = lane & 3;
    const int row0 = blockIdx.x * 64;
    const bool useAff = (pstats != nullptr);

    if (useAff && t < D) {
        float m  = pstats[t] * invN;
        float var = pstats[D + t] * invN - m * m;
        float sc = pg[t] * rsqrtf(var + 1e-5f);
        sAff[t]     = sc;
        sAff[D + t] = pb[t] - m * sc;
    }
    if (useAff) __syncthreads();

    // fused CSR gather from fp32 features, 16 lanes/node, 4x pipelined
#pragma unroll
    for (int pass = 0; pass < 4; pass++) {
        int r = pass * 16 + (t >> 4);
        int node = row0 + r;
        int c4 = (t & 15) << 2;
        float4 acc = make_float4(0.f, 0.f, 0.f, 0.f);
        if (node < nrows) {
            acc = *(const float4*)(feat + (size_t)node * D + c4);
            int s = __ldg(g_ptr + node), e = __ldg(g_ptr + node + 1);
            int j = s;
            for (; j + 4 <= e; j += 4) {
                int s0 = __ldg(g_csr + j + 0);
                int s1 = __ldg(g_csr + j + 1);
                int s2 = __ldg(g_csr + j + 2);
                int s3 = __ldg(g_csr + j + 3);
                float4 v0 = *(const float4*)(feat + (size_t)s0 * D + c4);
                float4 v1 = *(const float4*)(feat + (size_t)s1 * D + c4);
                float4 v2 = *(const float4*)(feat + (size_t)s2 * D + c4);
                float4 v3 = *(const float4*)(feat + (size_t)s3 * D + c4);
                acc.x += v0.x + v1.x + v2.x + v3.x;
                acc.y += v0.y + v1.y + v2.y + v3.y;
                acc.z += v0.z + v1.z + v2.z + v3.z;
                acc.w += v0.w + v1.w + v2.w + v3.w;
            }
            for (; j < e; j++) {
                int sv = __ldg(g_csr + j);
                float4 v = *(const float4*)(feat + (size_t)sv * D + c4);
                acc.x += v.x; acc.y += v.y; acc.z += v.z; acc.w += v.w;
            }
            if (useAff) {
                float cnt = (float)(e - s + 1);
                acc.x = sAff[c4 + 0] * acc.x + cnt * sAff[D + c4 + 0];
                acc.y = sAff[c4 + 1] * acc.y + cnt * sAff[D + c4 + 1];
                acc.z = sAff[c4 + 2] * acc.z + cnt * sAff[D + c4 + 2];
                acc.w = sAff[c4 + 3] * acc.w + cnt * sAff[D + c4 + 3];
            }
        }
        int idx = r * HP + (c4 >> 1);
        split_h2(acc.x, acc.y, sAh[idx], sAl[idx]);
        split_h2(acc.z, acc.w, sAh[idx + 1], sAl[idx + 1]);
    }

    uint32_t wh[2][4][2], wl[2][4][2];
    load_wfrags(W1, wn, gid, tg, wh, wl);

    float acc[2][2][4];
#pragma unroll
    for (int mt = 0; mt < 2; mt++)
#pragma unroll
        for (int nt = 0; nt < 2; nt++)
#pragma unroll
            for (int i = 0; i < 4; i++) acc[mt][nt][i] = 0.f;

    __syncthreads();
    gemm_f16x2(sAh, sAl, wm, gid, tg, wh, wl, acc);

    __syncthreads();
#pragma unroll
    for (int nt = 0; nt < 2; nt++) {
        int cb = wn * 16 + nt * 8 + 2 * tg;
        float bx = __ldg(b1 + cb), by = __ldg(b1 + cb + 1);
        int ci = (cb >> 1);
#pragma unroll
        for (int mt = 0; mt < 2; mt++) {
#pragma unroll
            for (int hh = 0; hh < 2; hh++) {
                int r = wm * 32 + mt * 16 + gid + hh * 8;
                float ox = fmaxf(acc[mt][nt][2 * hh + 0] + bx, 0.f);
                float oy = fmaxf(acc[mt][nt][2 * hh + 1] + by, 0.f);
                split_h2(ox, oy, sAh[r * HP + ci], sAl[r * HP + ci]);
            }
        }
    }
    load_wfrags(W2, wn, gid, tg, wh, wl);
#pragma unroll
    for (int mt = 0; mt < 2; mt++)
#pragma unroll
        for (int nt = 0; nt < 2; nt++)
#pragma unroll
            for (int i = 0; i < 4; i++) acc[mt][nt][i] = 0.f;
    __syncthreads();
    gemm_f16x2(sAh, sAl, wm, gid, tg, wh, wl, acc);

    epilogue(acc, b2, outF, stats, row0, wm, wn, gid, tg, nrows);
}

// ---------------------------------------------------------------------------
// Heads kernel: load t2 tile + BN-3 affine (dense), then BOTH head GEMMs off
// the same smem tile. Writes pre-BN mu -> out[0:N*D), lv -> out[N*D:2*N*D).
__global__ void __launch_bounds__(256, 3) heads_kernel(
    const float* __restrict__ feat,
    const float* __restrict__ pstats, const float* __restrict__ pg,
    const float* __restrict__ pb,
    const float* __restrict__ muW, const float* __restrict__ mub,
    const float* __restrict__ lvW, const float* __restrict__ lvb,
    float* __restrict__ out,
    float* __restrict__ statsMu, float* __restrict__ statsLv,
    float invN, int nrows)
{
    __shared__ uint32_t sAh[64 * HP];
    __shared__ uint32_t sAl[64 * HP];
    __shared__ float    sAff[2 * D];

    const int t = threadIdx.x;
    const int lane = t & 31, wid = t >> 5;
    const int wm = wid & 1, wn = wid >> 1;
    const int gid = lane >> 2, tg = lane & 3;
    const int row0 = blockIdx.x * 64;

    if (t < D) {
        float m  = pstats[t] * invN;
        float var = pstats[D + t] * invN - m * m;
        float sc = pg[t] * rsqrtf(var + 1e-5f);
        sAff[t]     = sc;
        sAff[D + t] = pb[t] - m * sc;
    }
    __syncthreads();

    // dense tile load with BN-3 affine
    for (int i = t; i < 1024; i += 256) {
        int r = i >> 4, k4 = (i & 15) << 2;
        float4 v = make_float4(0.f, 0.f, 0.f, 0.f);
        if (row0 + r < nrows) {
            v = *(const float4*)(feat + (size_t)(row0 + r) * D + k4);
            v.x = sAff[k4 + 0] * v.x + sAff[D + k4 + 0];
            v.y = sAff[k4 + 1] * v.y + sAff[D + k4 + 1];
            v.z = sAff[k4 + 2] * v.z + sAff[D + k4 + 2];
            v.w = sAff[k4 + 3] * v.w + sAff[D + k4 + 3];
        }
        int idx = r * HP + (k4 >> 1);
        split_h2(v.x, v.y, sAh[idx], sAl[idx]);
        split_h2(v.z, v.w, sAh[idx + 1], sAl[idx + 1]);
    }

    uint32_t wh[2][4][2], wl[2][4][2];
    float acc[2][2][4];

    // mu head
    load_wfrags(muW, wn, gid, tg, wh, wl);
#pragma unroll
    for (int mt = 0; mt < 2; mt++)
#pragma unroll
        for (int nt = 0; nt < 2; nt++)
#pragma unroll
            for (int i = 0; i < 4; i++) acc[mt][nt][i] = 0.f;
    __syncthreads();
    gemm_f16x2(sAh, sAl, wm, gid, tg, wh, wl, acc);
    epilogue(acc, mub, out, statsMu, row0, wm, wn, gid, tg, nrows);

    // lv head (sA unchanged, read-only; no extra sync needed)
    load_wfrags(lvW, wn, gid, tg, wh, wl);
#pragma unroll
    for (int mt = 0; mt < 2; mt++)
#pragma unroll
        for (int nt = 0; nt < 2; nt++)
#pragma unroll
            for (int i = 0; i < 4; i++) acc[mt][nt][i] = 0.f;
    gemm_f16x2(sAh, sAl, wm, gid, tg, wh, wl, acc);
    epilogue(acc, lvb, out + (size_t)nrows * D, statsLv,
             row0, wm, wn, gid, tg, nrows);
}

// ---------------------------------------------------------------------------
// final BN for both halves of out, in place
__global__ void bn2_apply_kernel(float* __restrict__ out,
                                 const float* __restrict__ statsMu,
                                 const float* __restrict__ statsLv,
                                 const float* __restrict__ mug,
                                 const float* __restrict__ mubeta,
                                 const float* __restrict__ lvg,
                                 const float* __restrict__ lvbeta,
                                 float invN, int total4)
{
    int i = blockIdx.x * blockDim.x + threadIdx.x;
    if (i >= 2 * total4) return;
    bool isLv = (i >= total4);
    const float* stats = isLv ? statsLv : statsMu;
    const float* g = isLv ? lvg : mug;
    const float* b = isLv ? lvbeta : mubeta;
    int c = (i << 2) & 63;
    float4 v = ((const float4*)out)[i];
    float4 y;
#pragma unroll
    for (int j = 0; j < 4; j++) {
        float m  = stats[c + j] * invN;
        float var = stats[D + c + j] * invN - m * m;
        float sc = g[c + j] * rsqrtf(var + 1e-5f);
        float sh = b[c + j] - m * sc;
        (&y.x)[j] = (&v.x)[j] * sc + sh;
    }
    ((float4*)out)[i] = y;
}

// ---------------------------------------------------------------------------
extern "C" void kernel_launch(void* const* d_in, const int* in_sizes, int n_in,
                              void* d_out, int out_size)
{
    const float* x      = (const float*)d_in[0];
    const int*   ei     = (const int*)d_in[1];   // int32 (JAX downcast)
    const float* W1     = (const float*)d_in[3];
    const float* b1     = (const float*)d_in[4];
    const float* W2     = (const float*)d_in[5];
    const float* b2     = (const float*)d_in[6];
    const float* bng    = (const float*)d_in[7];
    const float* bnb    = (const float*)d_in[8];
    const float* muW    = (const float*)d_in[9];
    const float* mub    = (const float*)d_in[10];
    const float* lvW    = (const float*)d_in[11];
    const float* lvb    = (const float*)d_in[12];
    const float* mug    = (const float*)d_in[13];
    const float* mubeta = (const float*)d_in[14];
    const float* lvg    = (const float*)d_in[15];
    const float* lvbeta = (const float*)d_in[16];
    float* out = (float*)d_out;

    const int n = in_sizes[0] / D;
    const int E = in_sizes[1] / 2;
    const float invN = 1.0f / (float)n;
    const int total4 = n * (D / 4);
    const int gb = (n + 63) / 64;
    const int ebE = (E + 255) / 256;
    const int nb_scan = (n + 2047) / 2048;

    float *hbuf, *tbuf, *sbuf;
    cudaGetSymbolAddress((void**)&hbuf, g_h);
    cudaGetSymbolAddress((void**)&tbuf, g_t2);
    cudaGetSymbolAddress((void**)&sbuf, g_stats);

    zero_kernel<<<(n + 255) / 256, 256>>>(n);

    // build CSR (dst -> list of src)
    hist_kernel<<<ebE, 256>>>(ei, E);
    scan1_kernel<<<nb_scan, 512>>>(n);
    scan2_kernel<<<1, 64>>>(nb_scan);
    scan3_kernel<<<(n + 256) / 256, 256>>>(n, E);
    fill_kernel<<<ebE, 256>>>(ei, E);

    // layer 1: gather x, no affine -> t2 (pre-BN, fp32)
    mlp_kernel<<<gb, 256>>>(
        x, nullptr, nullptr, nullptr,
        W1, b1, W2, b2, tbuf, sbuf, invN, n);
    // layer 2: gather t2 + layer-1 affine -> h
    mlp_kernel<<<gb, 256>>>(
        tbuf, sbuf, bng, bnb,
        W1 + 4096, b1 + 64, W2 + 4096, b2 + 64, hbuf, sbuf + 128, invN, n);
    // layer 3: gather h + layer-2 affine -> t2
    mlp_kernel<<<gb, 256>>>(
        hbuf, sbuf + 128, bng + 64, bnb + 64,
        W1 + 8192, b1 + 128, W2 + 8192, b2 + 128, tbuf, sbuf + 256, invN, n);

    // heads: BN-3 affine fused into tile load; both GEMMs; pre-BN -> out
    heads_kernel<<<gb, 256>>>(
        tbuf, sbuf + 256, bng + 128, bnb + 128,
        muW, mub, lvW, lvb, out, sbuf + 3 * 128, sbuf + 4 * 128, invN, n);

    // final BN on both halves (in place)
    bn2_apply_kernel<<<(2 * total4 + 255) / 256, 256>>>(
        out, sbuf + 3 * 128, sbuf + 4 * 128,
        mug, mubeta, lvg, lvbeta, invN, total4);
}